// round 1
// baseline (speedup 1.0000x reference)
#include <cuda_runtime.h>

#define B_    4096
#define D_    1024
#define NI    15
#define NL    16
#define NH    256
#define NC    100
#define HC    4096   // NL*NH
#define EPSF  1e-10f
#define KSPLIT 4
#define KCH   (HC / KSPLIT)

// ---- scratch (device globals; no allocation allowed) ----
__device__ float g_split[NI * B_];                 // sigmoid(split) [n][b]
__device__ float g_p[NL * B_];                     // leaf probs [l][b]
__device__ float g_w2cat[NC * HC];                 // [c][l*256+h]
__device__ float g_hs[(size_t)B_ * HC];            // scaled relu hidden [b][l*256+h]  (64 MB)
__device__ float g_part[KSPLIT][(size_t)B_ * 128]; // split-K partials (padded N=128)

// ============================================================
// Kernel 1: fused gumbel-softmax gate + split sigmoid.
// softmax normalizer cancels: agg = sum(e*x*fw)/sum(e), single pass.
// ============================================================
__global__ void k_gumbel_split(const float* __restrict__ x,
                               const float* __restrict__ u,
                               const float* __restrict__ fl,
                               const float* __restrict__ thr,
                               const float* __restrict__ fw) {
    int nb = blockIdx.x;            // n*B + b
    int n  = nb / B_;
    int b  = nb % B_;
    const float* urow = u  + (size_t)nb * D_;
    const float* xrow = x  + (size_t)b  * D_;
    const float* flr  = fl + n * D_;
    const float* fwr  = fw + n * D_;

    float s0 = 0.f, s1 = 0.f;
    for (int d = threadIdx.x; d < D_; d += blockDim.x) {
        float uv = urow[d];
        float t  = -__logf(uv + EPSF);
        float g  = -__logf(t  + EPSF);
        float e  = __expf(flr[d] + g);   // tau = 1
        s0 += e;
        s1 += e * xrow[d] * fwr[d];
    }
    #pragma unroll
    for (int off = 16; off; off >>= 1) {
        s0 += __shfl_down_sync(0xffffffffu, s0, off);
        s1 += __shfl_down_sync(0xffffffffu, s1, off);
    }
    __shared__ float sh0[4], sh1[4];
    int w = threadIdx.x >> 5;
    if ((threadIdx.x & 31) == 0) { sh0[w] = s0; sh1[w] = s1; }
    __syncthreads();
    if (threadIdx.x == 0) {
        float a0 = sh0[0] + sh0[1] + sh0[2] + sh0[3];
        float a1 = sh1[0] + sh1[1] + sh1[2] + sh1[3];
        float agg = a1 / a0;
        float z = agg - thr[n];
        g_split[nb] = 1.f / (1.f + __expf(-z));
    }
}

// ============================================================
// Kernel 2: leaf routing probabilities (heap traversal).
// ============================================================
__global__ void k_leaf_probs() {
    int b = blockIdx.x * blockDim.x + threadIdx.x;
    if (b >= B_) return;
    float s[NI];
    #pragma unroll
    for (int i = 0; i < NI; i++) s[i] = g_split[i * B_ + b];
    #pragma unroll
    for (int l = 0; l < NL; l++) {
        float p = 1.f;
        int pos = 0;
        #pragma unroll
        for (int k = 0; k < 4; k++) {
            int bit = (l >> (3 - k)) & 1;
            float sv = s[(1 << k) - 1 + pos];
            p *= bit ? sv : (1.f - sv);
            pos = 2 * pos + bit;
        }
        g_p[l * B_ + b] = p;
    }
}

// ============================================================
// Kernel 3: pack W2 [16][100][256] -> W2cat [100][4096] (K contiguous)
// ============================================================
__global__ void k_pack_w2(const float* __restrict__ W2) {
    int idx = blockIdx.x * blockDim.x + threadIdx.x;
    if (idx >= NC * HC) return;
    int c = idx / HC;
    int j = idx - c * HC;
    int l = j >> 8;
    int h = j & 255;
    g_w2cat[idx] = W2[((size_t)l * NC + c) * NH + h];
}

// ============================================================
// Kernel 4: GEMM1  Hs[b][n] = relu(x @ W1flat^T + b1) * p[n>>8][b]
// 128x128x16 tile, 256 threads, 8x8 microtile.
// ============================================================
__global__ __launch_bounds__(256) void k_gemm1(const float* __restrict__ A,   // x [B][D]
                                               const float* __restrict__ Bm,  // W1 flat [HC][D]
                                               const float* __restrict__ b1) {
    __shared__ float As[16][128];
    __shared__ float Bs[16][128];
    int m0 = blockIdx.y * 128;
    int n0 = blockIdx.x * 128;
    int tid = threadIdx.x;
    int tr = tid >> 4, tc = tid & 15;
    int lr = tid >> 2;           // 0..63
    int lc = (tid & 3) << 2;     // 0,4,8,12

    float acc[8][8] = {};

    for (int k0 = 0; k0 < D_; k0 += 16) {
        #pragma unroll
        for (int rr = 0; rr < 2; rr++) {
            int r = lr + rr * 64;
            float4 va = *(const float4*)&A [(size_t)(m0 + r) * D_ + k0 + lc];
            As[lc + 0][r] = va.x; As[lc + 1][r] = va.y;
            As[lc + 2][r] = va.z; As[lc + 3][r] = va.w;
            float4 vb = *(const float4*)&Bm[(size_t)(n0 + r) * D_ + k0 + lc];
            Bs[lc + 0][r] = vb.x; Bs[lc + 1][r] = vb.y;
            Bs[lc + 2][r] = vb.z; Bs[lc + 3][r] = vb.w;
        }
        __syncthreads();
        #pragma unroll
        for (int kk = 0; kk < 16; kk++) {
            float ar[8], br[8];
            #pragma unroll
            for (int i = 0; i < 8; i++) ar[i] = As[kk][tr * 8 + i];
            #pragma unroll
            for (int j = 0; j < 8; j++) br[j] = Bs[kk][tc * 8 + j];
            #pragma unroll
            for (int i = 0; i < 8; i++)
                #pragma unroll
                for (int j = 0; j < 8; j++)
                    acc[i][j] += ar[i] * br[j];
        }
        __syncthreads();
    }

    #pragma unroll
    for (int i = 0; i < 8; i++) {
        int m = m0 + tr * 8 + i;
        #pragma unroll
        for (int j = 0; j < 8; j++) {
            int n = n0 + tc * 8 + j;
            float v = acc[i][j] + b1[n];
            v = fmaxf(v, 0.f);
            v *= g_p[(n >> 8) * B_ + m];
            g_hs[(size_t)m * HC + n] = v;
        }
    }
}

// ============================================================
// Kernel 5: GEMM2 split-K partials: part[s][b][c] = Hs_chunk @ W2cat^T
// 64x128(->100)x16 tile, split-K=4.
// ============================================================
__global__ __launch_bounds__(256) void k_gemm2() {
    __shared__ float As[16][64];
    __shared__ float Bs[16][128];
    int m0 = blockIdx.x * 64;
    int ks = blockIdx.y * KCH;
    int tid = threadIdx.x;
    int tr = tid >> 4, tc = tid & 15;   // tr: 4 rows each, tc: 8 cols each
    int lr = tid >> 2;                  // 0..63
    int lc = (tid & 3) << 2;

    float acc[4][8] = {};

    for (int k0 = ks; k0 < ks + KCH; k0 += 16) {
        float4 va = *(const float4*)&g_hs[(size_t)(m0 + lr) * HC + k0 + lc];
        As[lc + 0][lr] = va.x; As[lc + 1][lr] = va.y;
        As[lc + 2][lr] = va.z; As[lc + 3][lr] = va.w;
        #pragma unroll
        for (int rr = 0; rr < 2; rr++) {
            int r = lr + rr * 64;
            float4 vb = (r < NC)
                ? *(const float4*)&g_w2cat[(size_t)r * HC + k0 + lc]
                : make_float4(0.f, 0.f, 0.f, 0.f);
            Bs[lc + 0][r] = vb.x; Bs[lc + 1][r] = vb.y;
            Bs[lc + 2][r] = vb.z; Bs[lc + 3][r] = vb.w;
        }
        __syncthreads();
        #pragma unroll
        for (int kk = 0; kk < 16; kk++) {
            float ar[4], br[8];
            #pragma unroll
            for (int i = 0; i < 4; i++) ar[i] = As[kk][tr * 4 + i];
            #pragma unroll
            for (int j = 0; j < 8; j++) br[j] = Bs[kk][tc * 8 + j];
            #pragma unroll
            for (int i = 0; i < 4; i++)
                #pragma unroll
                for (int j = 0; j < 8; j++)
                    acc[i][j] += ar[i] * br[j];
        }
        __syncthreads();
    }

    #pragma unroll
    for (int i = 0; i < 4; i++) {
        int m = m0 + tr * 4 + i;
        #pragma unroll
        for (int j = 0; j < 8; j++) {
            int n = tc * 8 + j;
            g_part[blockIdx.y][(size_t)m * 128 + n] = acc[i][j];
        }
    }
}

// ============================================================
// Kernel 6: reduce split-K partials + leaf-weighted b2 bias
// ============================================================
__global__ void k_reduce(const float* __restrict__ b2, float* __restrict__ out) {
    int idx = blockIdx.x * blockDim.x + threadIdx.x;
    if (idx >= B_ * NC) return;
    int b = idx / NC;
    int c = idx - b * NC;
    float v = 0.f;
    #pragma unroll
    for (int s = 0; s < KSPLIT; s++) v += g_part[s][(size_t)b * 128 + c];
    float bias = 0.f;
    #pragma unroll
    for (int l = 0; l < NL; l++) bias += g_p[l * B_ + b] * b2[l * NC + c];
    out[idx] = v + bias;
}

extern "C" void kernel_launch(void* const* d_in, const int* in_sizes, int n_in,
                              void* d_out, int out_size) {
    const float* x   = (const float*)d_in[0];
    const float* u   = (const float*)d_in[1];
    const float* fl  = (const float*)d_in[2];
    const float* thr = (const float*)d_in[3];
    const float* fw  = (const float*)d_in[4];
    const float* W1  = (const float*)d_in[5];
    const float* b1  = (const float*)d_in[6];
    const float* W2  = (const float*)d_in[7];
    const float* b2  = (const float*)d_in[8];
    float* out = (float*)d_out;

    k_gumbel_split<<<NI * B_, 128>>>(x, u, fl, thr, fw);
    k_leaf_probs<<<B_ / 256, 256>>>();
    k_pack_w2<<<(NC * HC + 255) / 256, 256>>>(W2);
    k_gemm1<<<dim3(HC / 128, B_ / 128), 256>>>(x, W1, b1);
    k_gemm2<<<dim3(B_ / 64, KSPLIT), 256>>>();
    k_reduce<<<(B_ * NC + 255) / 256, 256>>>(b2, out);
}

// round 3
// speedup vs baseline: 1.8673x; 1.8673x over previous
#include <cuda_runtime.h>
#include <cuda_bf16.h>
#include <cstdint>

#define B_    4096
#define D_    1024
#define NI    15
#define NL    16
#define NH    256
#define NC    100
#define HC    4096
#define EPSF  1e-10f
#define KSPLIT 4
#define KCH   (HC / KSPLIT)

// GEMM1 tiling (HMMA path)
#define TILE_M 128
#define TILE_N 128
#define KCHUNK 64                       // bf16 elems per k-stage (128 bytes/row)
#define NITER  (D_ / KCHUNK)            // 16
#define BUF_BYTES (128 * 128)           // one operand tile: 128 rows x 128B = 16KB
#define STAGE_BYTES (4 * BUF_BYTES)     // Ah, Al, Bh, Bl = 64KB
#define SMEM_TOTAL (2 * STAGE_BYTES)    // 128KB double-buffered

// ---- scratch (device globals) ----
__device__ float g_split[NI * B_];
__device__ float g_p[NL * B_];
__device__ float g_w2cat[NC * HC];
__device__ float g_hs[(size_t)B_ * HC];
__device__ float g_part[KSPLIT][(size_t)B_ * 128];
__device__ __nv_bfloat16 g_xh[(size_t)B_ * D_];
__device__ __nv_bfloat16 g_xl[(size_t)B_ * D_];
__device__ __nv_bfloat16 g_wh[(size_t)HC * D_];
__device__ __nv_bfloat16 g_wl[(size_t)HC * D_];

// ============================================================
// helpers
// ============================================================
__device__ __forceinline__ uint32_t smem_to_u32(const void* p) {
    uint32_t a;
    asm("{ .reg .u64 t; cvta.to.shared.u64 t, %1; cvt.u32.u64 %0, t; }" : "=r"(a) : "l"(p));
    return a;
}
__device__ __forceinline__ void cp_async16(uint32_t dst, const void* src) {
    asm volatile("cp.async.cg.shared.global [%0], [%1], 16;" :: "r"(dst), "l"(src));
}
__device__ __forceinline__ void cp_commit() { asm volatile("cp.async.commit_group;"); }
template<int N> __device__ __forceinline__ void cp_wait() {
    asm volatile("cp.async.wait_group %0;" :: "n"(N));
}
__device__ __forceinline__ void ldm_x4(uint32_t& r0, uint32_t& r1, uint32_t& r2, uint32_t& r3, uint32_t addr) {
    asm volatile("ldmatrix.sync.aligned.m8n8.x4.shared.b16 {%0,%1,%2,%3}, [%4];"
                 : "=r"(r0), "=r"(r1), "=r"(r2), "=r"(r3) : "r"(addr));
}
__device__ __forceinline__ void ldm_x2(uint32_t& r0, uint32_t& r1, uint32_t addr) {
    asm volatile("ldmatrix.sync.aligned.m8n8.x2.shared.b16 {%0,%1}, [%2];"
                 : "=r"(r0), "=r"(r1) : "r"(addr));
}
__device__ __forceinline__ void mma_bf16(float* d, const uint32_t* a, const uint32_t* b) {
    asm volatile("mma.sync.aligned.m16n8k16.row.col.f32.bf16.bf16.f32 "
                 "{%0,%1,%2,%3}, {%4,%5,%6,%7}, {%8,%9}, {%0,%1,%2,%3};"
                 : "+f"(d[0]), "+f"(d[1]), "+f"(d[2]), "+f"(d[3])
                 : "r"(a[0]), "r"(a[1]), "r"(a[2]), "r"(a[3]), "r"(b[0]), "r"(b[1]));
}

// ============================================================
// fp32 -> bf16 hi/lo split
// ============================================================
__global__ void k_split(const float* __restrict__ s, __nv_bfloat16* __restrict__ hi,
                        __nv_bfloat16* __restrict__ lo, int n4) {
    int i = blockIdx.x * blockDim.x + threadIdx.x;
    if (i >= n4) return;
    float4 v = ((const float4*)s)[i];
    __nv_bfloat16 h0 = __float2bfloat16_rn(v.x), h1 = __float2bfloat16_rn(v.y);
    __nv_bfloat16 h2 = __float2bfloat16_rn(v.z), h3 = __float2bfloat16_rn(v.w);
    __nv_bfloat16 l0 = __float2bfloat16_rn(v.x - __bfloat162float(h0));
    __nv_bfloat16 l1 = __float2bfloat16_rn(v.y - __bfloat162float(h1));
    __nv_bfloat16 l2 = __float2bfloat16_rn(v.z - __bfloat162float(h2));
    __nv_bfloat16 l3 = __float2bfloat16_rn(v.w - __bfloat162float(h3));
    ((__nv_bfloat162*)hi)[2*i]   = __nv_bfloat162(h0, h1);
    ((__nv_bfloat162*)hi)[2*i+1] = __nv_bfloat162(h2, h3);
    ((__nv_bfloat162*)lo)[2*i]   = __nv_bfloat162(l0, l1);
    ((__nv_bfloat162*)lo)[2*i+1] = __nv_bfloat162(l2, l3);
}

// ============================================================
// Kernel 1: gumbel gate + split sigmoid (warp per row)
// ============================================================
__global__ void k_gumbel_split(const float* __restrict__ x,
                               const float* __restrict__ u,
                               const float* __restrict__ fl,
                               const float* __restrict__ thr,
                               const float* __restrict__ fw) {
    int row  = blockIdx.x * 8 + (threadIdx.x >> 5);
    int lane = threadIdx.x & 31;
    int n = row / B_;
    int b = row - n * B_;
    const float4* u4  = (const float4*)(u  + (size_t)row * D_);
    const float4* x4  = (const float4*)(x  + (size_t)b   * D_);
    const float4* fl4 = (const float4*)(fl + n * D_);
    const float4* fw4 = (const float4*)(fw + n * D_);

    float s0 = 0.f, s1 = 0.f;
    #pragma unroll
    for (int i = 0; i < 8; i++) {
        int idx = i * 32 + lane;
        float4 uv = u4[idx], xv = x4[idx], flv = fl4[idx], fwv = fw4[idx];
        float e;
        e = __expf(flv.x - __logf(-__logf(uv.x + EPSF) + EPSF)); s0 += e; s1 += e * xv.x * fwv.x;
        e = __expf(flv.y - __logf(-__logf(uv.y + EPSF) + EPSF)); s0 += e; s1 += e * xv.y * fwv.y;
        e = __expf(flv.z - __logf(-__logf(uv.z + EPSF) + EPSF)); s0 += e; s1 += e * xv.z * fwv.z;
        e = __expf(flv.w - __logf(-__logf(uv.w + EPSF) + EPSF)); s0 += e; s1 += e * xv.w * fwv.w;
    }
    #pragma unroll
    for (int off = 16; off; off >>= 1) {
        s0 += __shfl_down_sync(0xffffffffu, s0, off);
        s1 += __shfl_down_sync(0xffffffffu, s1, off);
    }
    if (lane == 0) {
        float z = s1 / s0 - thr[n];
        g_split[row] = 1.f / (1.f + __expf(-z));
    }
}

// ============================================================
// Kernel 2: leaf routing probabilities
// ============================================================
__global__ void k_leaf_probs() {
    int b = blockIdx.x * blockDim.x + threadIdx.x;
    if (b >= B_) return;
    float s[NI];
    #pragma unroll
    for (int i = 0; i < NI; i++) s[i] = g_split[i * B_ + b];
    #pragma unroll
    for (int l = 0; l < NL; l++) {
        float p = 1.f;
        int pos = 0;
        #pragma unroll
        for (int k = 0; k < 4; k++) {
            int bit = (l >> (3 - k)) & 1;
            float sv = s[(1 << k) - 1 + pos];
            p *= bit ? sv : (1.f - sv);
            pos = 2 * pos + bit;
        }
        g_p[l * B_ + b] = p;
    }
}

// ============================================================
// Kernel 3: pack W2 [16][100][256] -> [100][4096]
// ============================================================
__global__ void k_pack_w2(const float* __restrict__ W2) {
    int idx = blockIdx.x * blockDim.x + threadIdx.x;
    if (idx >= NC * HC) return;
    int c = idx / HC;
    int j = idx - c * HC;
    int l = j >> 8;
    int h = j & 255;
    g_w2cat[idx] = W2[((size_t)l * NC + c) * NH + h];
}

// ============================================================
// Kernel 4: HMMA bf16 3-split GEMM1 + fused relu/bias/p epilogue
//   Hs[m][n] = relu(x@W1^T + b1)[m][n] * p[n>>8][m]
// block tile 128x128x64, 8 warps (2x4), warp tile 64x32
// smem: per stage {Ah, Al, Bh, Bl} 128 rows x 128B, XOR-swizzled
// ============================================================
__device__ __forceinline__ void stage_prefetch(uint32_t sbase, int stage,
                                               const __nv_bfloat16* Ah, const __nv_bfloat16* Al,
                                               const __nv_bfloat16* Bh, const __nv_bfloat16* Bl,
                                               int m0, int n0, int k0, int tid) {
    int r  = tid >> 1;              // 0..127
    int cs = (tid & 1) * 4;         // 0 or 4
    uint32_t st = sbase + stage * STAGE_BYTES;
    const __nv_bfloat16* srcs[4] = {
        Ah + (size_t)(m0 + r) * D_ + k0,
        Al + (size_t)(m0 + r) * D_ + k0,
        Bh + (size_t)(n0 + r) * D_ + k0,
        Bl + (size_t)(n0 + r) * D_ + k0
    };
    #pragma unroll
    for (int buf = 0; buf < 4; buf++) {
        uint32_t rowbase = st + buf * BUF_BYTES + r * 128;
        #pragma unroll
        for (int c = cs; c < cs + 4; c++) {
            uint32_t phys = (uint32_t)(c ^ (r & 7));
            cp_async16(rowbase + phys * 16, srcs[buf] + c * 8);
        }
    }
}

__global__ void __launch_bounds__(256, 1) k_gemm1_tc(const float* __restrict__ b1) {
    extern __shared__ char smem[];
    uint32_t sbase = smem_to_u32(smem);
    int tid = threadIdx.x;
    int wid = tid >> 5, lane = tid & 31;
    int warp_m = wid & 1, warp_n = wid >> 1;
    int m_w = warp_m * 64, n_w = warp_n * 32;
    int m0 = blockIdx.y * TILE_M;
    int n0 = blockIdx.x * TILE_N;

    float acc[4][4][4] = {};

    stage_prefetch(sbase, 0, g_xh, g_xl, g_wh, g_wl, m0, n0, 0, tid);
    cp_commit();
    stage_prefetch(sbase, 1, g_xh, g_xl, g_wh, g_wl, m0, n0, KCHUNK, tid);
    cp_commit();

    for (int i = 0; i < NITER; i++) {
        int s = i & 1;
        cp_wait<1>();
        __syncthreads();

        uint32_t st = sbase + s * STAGE_BYTES;
        // ldmatrix base addresses per fragment type
        #pragma unroll
        for (int kk = 0; kk < 4; kk++) {
            int cbase = kk * 2;                 // 2 chunks of 8 bf16 per k16
            uint32_t ah[4][4], al[4][4], bh[4][2], bl[4][2];
            // A frags: rows m_w + mi*16 + (lane&15), chunk cbase + (lane>>4)
            #pragma unroll
            for (int mi = 0; mi < 4; mi++) {
                int r = m_w + mi * 16 + (lane & 15);
                uint32_t ch = (uint32_t)((cbase + (lane >> 4)) ^ (r & 7));
                uint32_t off = (uint32_t)r * 128 + ch * 16;
                ldm_x4(ah[mi][0], ah[mi][1], ah[mi][2], ah[mi][3], st + off);
                ldm_x4(al[mi][0], al[mi][1], al[mi][2], al[mi][3], st + BUF_BYTES + off);
            }
            // B frags: rows n_w + ni*8 + (lane&7), chunk cbase + ((lane>>3)&1)
            #pragma unroll
            for (int ni = 0; ni < 4; ni++) {
                int r = n_w + ni * 8 + (lane & 7);
                uint32_t ch = (uint32_t)((cbase + ((lane >> 3) & 1)) ^ (r & 7));
                uint32_t off = (uint32_t)r * 128 + ch * 16;
                ldm_x2(bh[ni][0], bh[ni][1], st + 2 * BUF_BYTES + off);
                ldm_x2(bl[ni][0], bl[ni][1], st + 3 * BUF_BYTES + off);
            }
            #pragma unroll
            for (int mi = 0; mi < 4; mi++)
                #pragma unroll
                for (int ni = 0; ni < 4; ni++) {
                    mma_bf16(acc[mi][ni], ah[mi], bh[ni]);
                    mma_bf16(acc[mi][ni], ah[mi], bl[ni]);
                    mma_bf16(acc[mi][ni], al[mi], bh[ni]);
                }
        }
        __syncthreads();
        if (i + 2 < NITER)
            stage_prefetch(sbase, s, g_xh, g_xl, g_wh, g_wl, m0, n0, (i + 2) * KCHUNK, tid);
        cp_commit();
    }

    // epilogue: thread holds (row=lane/4, col=2*(lane%4)) pattern per m16n8 tile
    int trow = lane >> 2;
    int tcol = (lane & 3) * 2;
    int leaf = n0 >> 8;
    #pragma unroll
    for (int mi = 0; mi < 4; mi++) {
        int mA = m0 + m_w + mi * 16 + trow;
        int mB = mA + 8;
        float pA = g_p[leaf * B_ + mA];
        float pB = g_p[leaf * B_ + mB];
        #pragma unroll
        for (int ni = 0; ni < 4; ni++) {
            int n = n0 + n_w + ni * 8 + tcol;
            float bv0 = __ldg(&b1[n]), bv1 = __ldg(&b1[n + 1]);
            float2 v0, v1;
            v0.x = fmaxf(acc[mi][ni][0] + bv0, 0.f) * pA;
            v0.y = fmaxf(acc[mi][ni][1] + bv1, 0.f) * pA;
            v1.x = fmaxf(acc[mi][ni][2] + bv0, 0.f) * pB;
            v1.y = fmaxf(acc[mi][ni][3] + bv1, 0.f) * pB;
            *(float2*)&g_hs[(size_t)mA * HC + n] = v0;
            *(float2*)&g_hs[(size_t)mB * HC + n] = v1;
        }
    }
}

// ============================================================
// Kernel 5: GEMM2 split-K partials (fp32 SIMT)
// ============================================================
__global__ __launch_bounds__(256) void k_gemm2() {
    __shared__ float As[16][64];
    __shared__ float Bs[16][128];
    int m0 = blockIdx.x * 64;
    int ks = blockIdx.y * KCH;
    int tid = threadIdx.x;
    int tr = tid >> 4, tc = tid & 15;
    int lr = tid >> 2;
    int lc = (tid & 3) << 2;

    float acc[4][8] = {};

    for (int k0 = ks; k0 < ks + KCH; k0 += 16) {
        float4 va = *(const float4*)&g_hs[(size_t)(m0 + lr) * HC + k0 + lc];
        As[lc + 0][lr] = va.x; As[lc + 1][lr] = va.y;
        As[lc + 2][lr] = va.z; As[lc + 3][lr] = va.w;
        #pragma unroll
        for (int rr = 0; rr < 2; rr++) {
            int r = lr + rr * 64;
            float4 vb = (r < NC)
                ? *(const float4*)&g_w2cat[(size_t)r * HC + k0 + lc]
                : make_float4(0.f, 0.f, 0.f, 0.f);
            Bs[lc + 0][r] = vb.x; Bs[lc + 1][r] = vb.y;
            Bs[lc + 2][r] = vb.z; Bs[lc + 3][r] = vb.w;
        }
        __syncthreads();
        #pragma unroll
        for (int kk = 0; kk < 16; kk++) {
            float ar[4], br[8];
            #pragma unroll
            for (int i = 0; i < 4; i++) ar[i] = As[kk][tr * 4 + i];
            #pragma unroll
            for (int j = 0; j < 8; j++) br[j] = Bs[kk][tc * 8 + j];
            #pragma unroll
            for (int i = 0; i < 4; i++)
                #pragma unroll
                for (int j = 0; j < 8; j++)
                    acc[i][j] += ar[i] * br[j];
        }
        __syncthreads();
    }

    #pragma unroll
    for (int i = 0; i < 4; i++) {
        int m = m0 + tr * 4 + i;
        #pragma unroll
        for (int j = 0; j < 8; j++)
            g_part[blockIdx.y][(size_t)m * 128 + tc * 8 + j] = acc[i][j];
    }
}

// ============================================================
// Kernel 6: reduce split-K + leaf-weighted b2
// ============================================================
__global__ void k_reduce(const float* __restrict__ b2, float* __restrict__ out) {
    int idx = blockIdx.x * blockDim.x + threadIdx.x;
    if (idx >= B_ * NC) return;
    int b = idx / NC;
    int c = idx - b * NC;
    float v = 0.f;
    #pragma unroll
    for (int s = 0; s < KSPLIT; s++) v += g_part[s][(size_t)b * 128 + c];
    float bias = 0.f;
    #pragma unroll
    for (int l = 0; l < NL; l++) bias += g_p[l * B_ + b] * b2[l * NC + c];
    out[idx] = v + bias;
}

extern "C" void kernel_launch(void* const* d_in, const int* in_sizes, int n_in,
                              void* d_out, int out_size) {
    const float* x   = (const float*)d_in[0];
    const float* u   = (const float*)d_in[1];
    const float* fl  = (const float*)d_in[2];
    const float* thr = (const float*)d_in[3];
    const float* fw  = (const float*)d_in[4];
    const float* W1  = (const float*)d_in[5];
    const float* b1  = (const float*)d_in[6];
    const float* W2  = (const float*)d_in[7];
    const float* b2  = (const float*)d_in[8];
    float* out = (float*)d_out;

    void *pxh, *pxl, *pwh, *pwl;
    cudaGetSymbolAddress(&pxh, g_xh);
    cudaGetSymbolAddress(&pxl, g_xl);
    cudaGetSymbolAddress(&pwh, g_wh);
    cudaGetSymbolAddress(&pwl, g_wl);

    cudaFuncSetAttribute(k_gemm1_tc, cudaFuncAttributeMaxDynamicSharedMemorySize, SMEM_TOTAL);

    k_split<<<(B_ * D_ / 4 + 255) / 256, 256>>>(x,  (__nv_bfloat16*)pxh, (__nv_bfloat16*)pxl, B_ * D_ / 4);
    k_split<<<(HC * D_ / 4 + 255) / 256, 256>>>(W1, (__nv_bfloat16*)pwh, (__nv_bfloat16*)pwl, HC * D_ / 4);

    k_gumbel_split<<<NI * B_ / 8, 256>>>(x, u, fl, thr, fw);
    k_leaf_probs<<<B_ / 256, 256>>>();
    k_pack_w2<<<(NC * HC + 255) / 256, 256>>>(W2);

    k_gemm1_tc<<<dim3(HC / TILE_N, B_ / TILE_M), 256, SMEM_TOTAL>>>(b1);

    k_gemm2<<<dim3(B_ / 64, KSPLIT), 256>>>();
    k_reduce<<<(B_ * NC + 255) / 256, 256>>>(b2, out);
}

// round 4
// speedup vs baseline: 2.4686x; 1.3220x over previous
#include <cuda_runtime.h>
#include <cuda_bf16.h>
#include <cstdint>

#define B_    4096
#define D_    1024
#define NI    15
#define NL    16
#define NH    256
#define NC    100
#define HC    4096
#define EPSF  1e-10f

// GEMM tiling (HMMA path)
#define TILE_M 128
#define TILE_N 128
#define KCHUNK 64                       // bf16 elems per k-stage (128 bytes/row)
#define NITER1 (D_ / KCHUNK)            // 16 (GEMM1)
#define KSPLIT2 8
#define KCH2   (HC / KSPLIT2)           // 512
#define NITER2 (KCH2 / KCHUNK)          // 8 (GEMM2)
#define BUF_BYTES (128 * 128)           // one operand tile: 128 rows x 128B = 16KB
#define STAGE_BYTES (4 * BUF_BYTES)     // Ah, Al, Bh, Bl = 64KB
#define NSTAGE 3
#define SMEM_TOTAL (NSTAGE * STAGE_BYTES) // 192KB

// ---- scratch (device globals) ----
__device__ float g_split[NI * B_];
__device__ float g_p[NL * B_];
__device__ float g_part[KSPLIT2][(size_t)B_ * 128];
__device__ __nv_bfloat16 g_xh[(size_t)B_ * D_];
__device__ __nv_bfloat16 g_xl[(size_t)B_ * D_];
__device__ __nv_bfloat16 g_wh[(size_t)HC * D_];
__device__ __nv_bfloat16 g_wl[(size_t)HC * D_];
__device__ __nv_bfloat16 g_hsh[(size_t)B_ * HC];
__device__ __nv_bfloat16 g_hsl[(size_t)B_ * HC];
__device__ __nv_bfloat16 g_w2h[(size_t)128 * HC];
__device__ __nv_bfloat16 g_w2l[(size_t)128 * HC];

// ============================================================
// helpers
// ============================================================
__device__ __forceinline__ uint32_t smem_to_u32(const void* p) {
    uint32_t a;
    asm("{ .reg .u64 t; cvta.to.shared.u64 t, %1; cvt.u32.u64 %0, t; }" : "=r"(a) : "l"(p));
    return a;
}
__device__ __forceinline__ void cp_async16(uint32_t dst, const void* src) {
    asm volatile("cp.async.cg.shared.global [%0], [%1], 16;" :: "r"(dst), "l"(src));
}
__device__ __forceinline__ void cp_commit() { asm volatile("cp.async.commit_group;"); }
template<int N> __device__ __forceinline__ void cp_wait() {
    asm volatile("cp.async.wait_group %0;" :: "n"(N));
}
__device__ __forceinline__ void ldm_x4(uint32_t& r0, uint32_t& r1, uint32_t& r2, uint32_t& r3, uint32_t addr) {
    asm volatile("ldmatrix.sync.aligned.m8n8.x4.shared.b16 {%0,%1,%2,%3}, [%4];"
                 : "=r"(r0), "=r"(r1), "=r"(r2), "=r"(r3) : "r"(addr));
}
__device__ __forceinline__ void ldm_x2(uint32_t& r0, uint32_t& r1, uint32_t addr) {
    asm volatile("ldmatrix.sync.aligned.m8n8.x2.shared.b16 {%0,%1}, [%2];"
                 : "=r"(r0), "=r"(r1) : "r"(addr));
}
__device__ __forceinline__ void mma_bf16(float* d, const uint32_t* a, const uint32_t* b) {
    asm volatile("mma.sync.aligned.m16n8k16.row.col.f32.bf16.bf16.f32 "
                 "{%0,%1,%2,%3}, {%4,%5,%6,%7}, {%8,%9}, {%0,%1,%2,%3};"
                 : "+f"(d[0]), "+f"(d[1]), "+f"(d[2]), "+f"(d[3])
                 : "r"(a[0]), "r"(a[1]), "r"(a[2]), "r"(a[3]), "r"(b[0]), "r"(b[1]));
}

// ============================================================
// fp32 -> bf16 hi/lo split
// ============================================================
__global__ void k_split(const float* __restrict__ s, __nv_bfloat16* __restrict__ hi,
                        __nv_bfloat16* __restrict__ lo, int n4) {
    int i = blockIdx.x * blockDim.x + threadIdx.x;
    if (i >= n4) return;
    float4 v = ((const float4*)s)[i];
    __nv_bfloat16 h0 = __float2bfloat16_rn(v.x), h1 = __float2bfloat16_rn(v.y);
    __nv_bfloat16 h2 = __float2bfloat16_rn(v.z), h3 = __float2bfloat16_rn(v.w);
    __nv_bfloat16 l0 = __float2bfloat16_rn(v.x - __bfloat162float(h0));
    __nv_bfloat16 l1 = __float2bfloat16_rn(v.y - __bfloat162float(h1));
    __nv_bfloat16 l2 = __float2bfloat16_rn(v.z - __bfloat162float(h2));
    __nv_bfloat16 l3 = __float2bfloat16_rn(v.w - __bfloat162float(h3));
    ((__nv_bfloat162*)hi)[2*i]   = __nv_bfloat162(h0, h1);
    ((__nv_bfloat162*)hi)[2*i+1] = __nv_bfloat162(h2, h3);
    ((__nv_bfloat162*)lo)[2*i]   = __nv_bfloat162(l0, l1);
    ((__nv_bfloat162*)lo)[2*i+1] = __nv_bfloat162(l2, l3);
}

// ============================================================
// Kernel 1: gumbel gate + split sigmoid (warp per row)
// ============================================================
__global__ void k_gumbel_split(const float* __restrict__ x,
                               const float* __restrict__ u,
                               const float* __restrict__ fl,
                               const float* __restrict__ thr,
                               const float* __restrict__ fw) {
    int row  = blockIdx.x * 8 + (threadIdx.x >> 5);
    int lane = threadIdx.x & 31;
    int n = row / B_;
    int b = row - n * B_;
    const float4* u4  = (const float4*)(u  + (size_t)row * D_);
    const float4* x4  = (const float4*)(x  + (size_t)b   * D_);
    const float4* fl4 = (const float4*)(fl + n * D_);
    const float4* fw4 = (const float4*)(fw + n * D_);

    float s0 = 0.f, s1 = 0.f;
    #pragma unroll
    for (int i = 0; i < 8; i++) {
        int idx = i * 32 + lane;
        float4 uv = u4[idx], xv = x4[idx], flv = fl4[idx], fwv = fw4[idx];
        float e;
        e = __expf(flv.x - __logf(-__logf(uv.x + EPSF) + EPSF)); s0 += e; s1 += e * xv.x * fwv.x;
        e = __expf(flv.y - __logf(-__logf(uv.y + EPSF) + EPSF)); s0 += e; s1 += e * xv.y * fwv.y;
        e = __expf(flv.z - __logf(-__logf(uv.z + EPSF) + EPSF)); s0 += e; s1 += e * xv.z * fwv.z;
        e = __expf(flv.w - __logf(-__logf(uv.w + EPSF) + EPSF)); s0 += e; s1 += e * xv.w * fwv.w;
    }
    #pragma unroll
    for (int off = 16; off; off >>= 1) {
        s0 += __shfl_down_sync(0xffffffffu, s0, off);
        s1 += __shfl_down_sync(0xffffffffu, s1, off);
    }
    if (lane == 0) {
        float z = s1 / s0 - thr[n];
        g_split[row] = 1.f / (1.f + __expf(-z));
    }
}

// ============================================================
// Kernel 2: leaf routing probabilities
// ============================================================
__global__ void k_leaf_probs() {
    int b = blockIdx.x * blockDim.x + threadIdx.x;
    if (b >= B_) return;
    float s[NI];
    #pragma unroll
    for (int i = 0; i < NI; i++) s[i] = g_split[i * B_ + b];
    #pragma unroll
    for (int l = 0; l < NL; l++) {
        float p = 1.f;
        int pos = 0;
        #pragma unroll
        for (int k = 0; k < 4; k++) {
            int bit = (l >> (3 - k)) & 1;
            float sv = s[(1 << k) - 1 + pos];
            p *= bit ? sv : (1.f - sv);
            pos = 2 * pos + bit;
        }
        g_p[l * B_ + b] = p;
    }
}

// ============================================================
// Kernel 3: pack W2 [16][100][256] -> bf16 hi/lo [128 pad][4096]
// ============================================================
__global__ void k_pack_w2(const float* __restrict__ W2) {
    int idx = blockIdx.x * blockDim.x + threadIdx.x;
    if (idx >= 128 * HC) return;
    int c = idx / HC;
    int j = idx - c * HC;
    int l = j >> 8;
    int h = j & 255;
    float v = (c < NC) ? W2[((size_t)l * NC + c) * NH + h] : 0.f;
    __nv_bfloat16 hi = __float2bfloat16_rn(v);
    __nv_bfloat16 lo = __float2bfloat16_rn(v - __bfloat162float(hi));
    g_w2h[idx] = hi;
    g_w2l[idx] = lo;
}

// ============================================================
// shared HMMA mainloop machinery
// ============================================================
template<int LD>
__device__ __forceinline__ void stage_prefetch(uint32_t sbase, int stage,
                                               const __nv_bfloat16* Ah, const __nv_bfloat16* Al,
                                               const __nv_bfloat16* Bh, const __nv_bfloat16* Bl,
                                               int m0, int n0, int k0, int tid) {
    int r  = tid >> 1;              // 0..127
    int cs = (tid & 1) * 4;         // 0 or 4
    uint32_t st = sbase + stage * STAGE_BYTES;
    const __nv_bfloat16* srcs[4] = {
        Ah + (size_t)(m0 + r) * LD + k0,
        Al + (size_t)(m0 + r) * LD + k0,
        Bh + (size_t)(n0 + r) * LD + k0,
        Bl + (size_t)(n0 + r) * LD + k0
    };
    #pragma unroll
    for (int buf = 0; buf < 4; buf++) {
        uint32_t rowbase = st + buf * BUF_BYTES + r * 128;
        #pragma unroll
        for (int c = cs; c < cs + 4; c++) {
            uint32_t phys = (uint32_t)(c ^ (r & 7));
            cp_async16(rowbase + phys * 16, srcs[buf] + c * 8);
        }
    }
}

// G2=false: GEMM1  x@W1^T (K=1024) + relu/bias/p epilogue -> hs bf16 hi/lo
// G2=true : GEMM2  hs@W2cat^T (split-K over 8) -> fp32 partials
template<bool G2>
__global__ void __launch_bounds__(256, 1) k_gemm_tc(const float* __restrict__ b1) {
    extern __shared__ char smem[];
    uint32_t sbase = smem_to_u32(smem);
    int tid = threadIdx.x;
    int wid = tid >> 5, lane = tid & 31;
    int warp_m = wid & 1, warp_n = wid >> 1;
    int m_w = warp_m * 64, n_w = warp_n * 32;
    int m0 = blockIdx.y * TILE_M;

    constexpr int LD    = G2 ? HC : D_;
    constexpr int niter = G2 ? NITER2 : NITER1;
    const __nv_bfloat16* Ah = G2 ? g_hsh : g_xh;
    const __nv_bfloat16* Al = G2 ? g_hsl : g_xl;
    const __nv_bfloat16* Bh = G2 ? g_w2h : g_wh;
    const __nv_bfloat16* Bl = G2 ? g_w2l : g_wl;
    int n0    = G2 ? 0 : blockIdx.x * TILE_N;
    int kbase = G2 ? blockIdx.x * KCH2 : 0;

    float acc[4][4][4] = {};

    stage_prefetch<LD>(sbase, 0, Ah, Al, Bh, Bl, m0, n0, kbase, tid);
    cp_commit();
    stage_prefetch<LD>(sbase, 1, Ah, Al, Bh, Bl, m0, n0, kbase + KCHUNK, tid);
    cp_commit();
    stage_prefetch<LD>(sbase, 2, Ah, Al, Bh, Bl, m0, n0, kbase + 2 * KCHUNK, tid);
    cp_commit();

    for (int i = 0; i < niter; i++) {
        int s = i % NSTAGE;
        cp_wait<2>();
        __syncthreads();

        uint32_t st = sbase + s * STAGE_BYTES;
        #pragma unroll
        for (int kk = 0; kk < 4; kk++) {
            int cbase = kk * 2;
            uint32_t ah[4][4], al[4][4], bh[4][2], bl[4][2];
            #pragma unroll
            for (int mi = 0; mi < 4; mi++) {
                int r = m_w + mi * 16 + (lane & 15);
                uint32_t ch = (uint32_t)((cbase + (lane >> 4)) ^ (r & 7));
                uint32_t off = (uint32_t)r * 128 + ch * 16;
                ldm_x4(ah[mi][0], ah[mi][1], ah[mi][2], ah[mi][3], st + off);
                ldm_x4(al[mi][0], al[mi][1], al[mi][2], al[mi][3], st + BUF_BYTES + off);
            }
            #pragma unroll
            for (int ni = 0; ni < 4; ni++) {
                int r = n_w + ni * 8 + (lane & 7);
                uint32_t ch = (uint32_t)((cbase + ((lane >> 3) & 1)) ^ (r & 7));
                uint32_t off = (uint32_t)r * 128 + ch * 16;
                ldm_x2(bh[ni][0], bh[ni][1], st + 2 * BUF_BYTES + off);
                ldm_x2(bl[ni][0], bl[ni][1], st + 3 * BUF_BYTES + off);
            }
            #pragma unroll
            for (int mi = 0; mi < 4; mi++)
                #pragma unroll
                for (int ni = 0; ni < 4; ni++) {
                    mma_bf16(acc[mi][ni], ah[mi], bh[ni]);
                    mma_bf16(acc[mi][ni], ah[mi], bl[ni]);
                    mma_bf16(acc[mi][ni], al[mi], bh[ni]);
                }
        }
        __syncthreads();
        if (i + NSTAGE < niter)
            stage_prefetch<LD>(sbase, s, Ah, Al, Bh, Bl, m0, n0, kbase + (i + NSTAGE) * KCHUNK, tid);
        cp_commit();
    }

    int trow = lane >> 2;
    int tcol = (lane & 3) * 2;
    if (!G2) {
        // relu/bias/p epilogue -> bf16 hi/lo hs
        int leaf = n0 >> 8;
        #pragma unroll
        for (int mi = 0; mi < 4; mi++) {
            int mA = m0 + m_w + mi * 16 + trow;
            int mB = mA + 8;
            float pA = g_p[leaf * B_ + mA];
            float pB = g_p[leaf * B_ + mB];
            #pragma unroll
            for (int ni = 0; ni < 4; ni++) {
                int n = n0 + n_w + ni * 8 + tcol;
                float bv0 = __ldg(&b1[n]), bv1 = __ldg(&b1[n + 1]);
                float v00 = fmaxf(acc[mi][ni][0] + bv0, 0.f) * pA;
                float v01 = fmaxf(acc[mi][ni][1] + bv1, 0.f) * pA;
                float v10 = fmaxf(acc[mi][ni][2] + bv0, 0.f) * pB;
                float v11 = fmaxf(acc[mi][ni][3] + bv1, 0.f) * pB;
                __nv_bfloat16 h00 = __float2bfloat16_rn(v00);
                __nv_bfloat16 h01 = __float2bfloat16_rn(v01);
                __nv_bfloat16 h10 = __float2bfloat16_rn(v10);
                __nv_bfloat16 h11 = __float2bfloat16_rn(v11);
                __nv_bfloat16 l00 = __float2bfloat16_rn(v00 - __bfloat162float(h00));
                __nv_bfloat16 l01 = __float2bfloat16_rn(v01 - __bfloat162float(h01));
                __nv_bfloat16 l10 = __float2bfloat16_rn(v10 - __bfloat162float(h10));
                __nv_bfloat16 l11 = __float2bfloat16_rn(v11 - __bfloat162float(h11));
                size_t iA = (size_t)mA * HC + n, iB = (size_t)mB * HC + n;
                *(__nv_bfloat162*)&g_hsh[iA] = __nv_bfloat162(h00, h01);
                *(__nv_bfloat162*)&g_hsl[iA] = __nv_bfloat162(l00, l01);
                *(__nv_bfloat162*)&g_hsh[iB] = __nv_bfloat162(h10, h11);
                *(__nv_bfloat162*)&g_hsl[iB] = __nv_bfloat162(l10, l11);
            }
        }
    } else {
        // raw fp32 partials
        float* part = g_part[blockIdx.x];
        #pragma unroll
        for (int mi = 0; mi < 4; mi++) {
            int mA = m0 + m_w + mi * 16 + trow;
            int mB = mA + 8;
            #pragma unroll
            for (int ni = 0; ni < 4; ni++) {
                int n = n_w + ni * 8 + tcol;
                *(float2*)&part[(size_t)mA * 128 + n] = make_float2(acc[mi][ni][0], acc[mi][ni][1]);
                *(float2*)&part[(size_t)mB * 128 + n] = make_float2(acc[mi][ni][2], acc[mi][ni][3]);
            }
        }
    }
}

// ============================================================
// Kernel 6: reduce split-K + leaf-weighted b2
// ============================================================
__global__ void k_reduce(const float* __restrict__ b2, float* __restrict__ out) {
    int idx = blockIdx.x * blockDim.x + threadIdx.x;
    if (idx >= B_ * NC) return;
    int b = idx / NC;
    int c = idx - b * NC;
    float v = 0.f;
    #pragma unroll
    for (int s = 0; s < KSPLIT2; s++) v += g_part[s][(size_t)b * 128 + c];
    float bias = 0.f;
    #pragma unroll
    for (int l = 0; l < NL; l++) bias += g_p[l * B_ + b] * b2[l * NC + c];
    out[idx] = v + bias;
}

extern "C" void kernel_launch(void* const* d_in, const int* in_sizes, int n_in,
                              void* d_out, int out_size) {
    const float* x   = (const float*)d_in[0];
    const float* u   = (const float*)d_in[1];
    const float* fl  = (const float*)d_in[2];
    const float* thr = (const float*)d_in[3];
    const float* fw  = (const float*)d_in[4];
    const float* W1  = (const float*)d_in[5];
    const float* b1  = (const float*)d_in[6];
    const float* W2  = (const float*)d_in[7];
    const float* b2  = (const float*)d_in[8];
    float* out = (float*)d_out;

    void *pxh, *pxl, *pwh, *pwl;
    cudaGetSymbolAddress(&pxh, g_xh);
    cudaGetSymbolAddress(&pxl, g_xl);
    cudaGetSymbolAddress(&pwh, g_wh);
    cudaGetSymbolAddress(&pwl, g_wl);

    cudaFuncSetAttribute(k_gemm_tc<false>, cudaFuncAttributeMaxDynamicSharedMemorySize, SMEM_TOTAL);
    cudaFuncSetAttribute(k_gemm_tc<true>,  cudaFuncAttributeMaxDynamicSharedMemorySize, SMEM_TOTAL);

    k_split<<<(B_ * D_ / 4 + 255) / 256, 256>>>(x,  (__nv_bfloat16*)pxh, (__nv_bfloat16*)pxl, B_ * D_ / 4);
    k_split<<<(HC * D_ / 4 + 255) / 256, 256>>>(W1, (__nv_bfloat16*)pwh, (__nv_bfloat16*)pwl, HC * D_ / 4);

    k_gumbel_split<<<NI * B_ / 8, 256>>>(x, u, fl, thr, fw);
    k_leaf_probs<<<B_ / 256, 256>>>();
    k_pack_w2<<<(128 * HC + 255) / 256, 256>>>(W2);

    k_gemm_tc<false><<<dim3(HC / TILE_N, B_ / TILE_M), 256, SMEM_TOTAL>>>(b1);
    k_gemm_tc<true><<<dim3(KSPLIT2, B_ / TILE_M), 256, SMEM_TOTAL>>>(nullptr);

    k_reduce<<<(B_ * NC + 255) / 256, 256>>>(b2, out);
}

// round 5
// speedup vs baseline: 2.5012x; 1.0132x over previous
#include <cuda_runtime.h>
#include <cuda_bf16.h>
#include <cstdint>

#define B_    4096
#define D_    1024
#define NI    15
#define NL    16
#define NH    256
#define NC    100
#define HC    4096
#define EPSF  1e-10f

// GEMM tiling (HMMA path)
#define TILE_M 128
#define TILE_N 128
#define KCHUNK 64                       // bf16 elems per k-stage (128 bytes/row)
#define NITER1 (D_ / KCHUNK)            // 16 (GEMM1)
#define KSPLIT2 8
#define KCH2   (HC / KSPLIT2)           // 512
#define NITER2 (KCH2 / KCHUNK)          // 8 (GEMM2)
#define BUF_BYTES (128 * 128)           // one operand tile: 128 rows x 128B = 16KB
#define STAGE_BYTES (4 * BUF_BYTES)     // Ah, Al, Bh, Bl = 64KB
#define NSTAGE 3
#define SMEM_TOTAL (NSTAGE * STAGE_BYTES) // 192KB

// ---- scratch (device globals) ----
__device__ float g_split[NI * B_];
__device__ float g_p[NL * B_];
__device__ float g_part[KSPLIT2][(size_t)B_ * 128];
__device__ __nv_bfloat16 g_xh[(size_t)B_ * D_];
__device__ __nv_bfloat16 g_xl[(size_t)B_ * D_];
__device__ __nv_bfloat16 g_wh[(size_t)HC * D_];
__device__ __nv_bfloat16 g_wl[(size_t)HC * D_];
__device__ __nv_bfloat16 g_hsh[(size_t)B_ * HC];
__device__ __nv_bfloat16 g_hsl[(size_t)B_ * HC];
__device__ __nv_bfloat16 g_w2h[(size_t)128 * HC];
__device__ __nv_bfloat16 g_w2l[(size_t)128 * HC];

// ============================================================
// helpers
// ============================================================
__device__ __forceinline__ uint32_t smem_to_u32(const void* p) {
    uint32_t a;
    asm("{ .reg .u64 t; cvta.to.shared.u64 t, %1; cvt.u32.u64 %0, t; }" : "=r"(a) : "l"(p));
    return a;
}
__device__ __forceinline__ void cp_async16(uint32_t dst, const void* src) {
    asm volatile("cp.async.cg.shared.global [%0], [%1], 16;" :: "r"(dst), "l"(src));
}
__device__ __forceinline__ void cp_commit() { asm volatile("cp.async.commit_group;"); }
template<int N> __device__ __forceinline__ void cp_wait() {
    asm volatile("cp.async.wait_group %0;" :: "n"(N));
}
__device__ __forceinline__ void ldm_x4(uint32_t& r0, uint32_t& r1, uint32_t& r2, uint32_t& r3, uint32_t addr) {
    asm volatile("ldmatrix.sync.aligned.m8n8.x4.shared.b16 {%0,%1,%2,%3}, [%4];"
                 : "=r"(r0), "=r"(r1), "=r"(r2), "=r"(r3) : "r"(addr));
}
__device__ __forceinline__ void mma_bf16(float* d, const uint32_t* a, const uint32_t* b) {
    asm volatile("mma.sync.aligned.m16n8k16.row.col.f32.bf16.bf16.f32 "
                 "{%0,%1,%2,%3}, {%4,%5,%6,%7}, {%8,%9}, {%0,%1,%2,%3};"
                 : "+f"(d[0]), "+f"(d[1]), "+f"(d[2]), "+f"(d[3])
                 : "r"(a[0]), "r"(a[1]), "r"(a[2]), "r"(a[3]), "r"(b[0]), "r"(b[1]));
}

// ============================================================
// Kernel 0: fp32 -> bf16 hi/lo split for BOTH x and W1 (one launch)
// ============================================================
#define N4X (B_ * D_ / 4)
#define N4W (HC * D_ / 4)
__global__ void k_split_all(const float* __restrict__ x, const float* __restrict__ w) {
    int i = blockIdx.x * blockDim.x + threadIdx.x;
    const float* s;
    __nv_bfloat16 *hi, *lo;
    int j;
    if (i < N4X) { s = x; hi = g_xh; lo = g_xl; j = i; }
    else if (i < N4X + N4W) { s = w; hi = g_wh; lo = g_wl; j = i - N4X; }
    else return;
    float4 v = ((const float4*)s)[j];
    __nv_bfloat16 h0 = __float2bfloat16_rn(v.x), h1 = __float2bfloat16_rn(v.y);
    __nv_bfloat16 h2 = __float2bfloat16_rn(v.z), h3 = __float2bfloat16_rn(v.w);
    __nv_bfloat16 l0 = __float2bfloat16_rn(v.x - __bfloat162float(h0));
    __nv_bfloat16 l1 = __float2bfloat16_rn(v.y - __bfloat162float(h1));
    __nv_bfloat16 l2 = __float2bfloat16_rn(v.z - __bfloat162float(h2));
    __nv_bfloat16 l3 = __float2bfloat16_rn(v.w - __bfloat162float(h3));
    ((__nv_bfloat162*)hi)[2*j]   = __nv_bfloat162(h0, h1);
    ((__nv_bfloat162*)hi)[2*j+1] = __nv_bfloat162(h2, h3);
    ((__nv_bfloat162*)lo)[2*j]   = __nv_bfloat162(l0, l1);
    ((__nv_bfloat162*)lo)[2*j+1] = __nv_bfloat162(l2, l3);
}

// ============================================================
// Kernel 1: gumbel gate + split sigmoid (warp per row)
// ============================================================
__global__ void k_gumbel_split(const float* __restrict__ x,
                               const float* __restrict__ u,
                               const float* __restrict__ fl,
                               const float* __restrict__ thr,
                               const float* __restrict__ fw) {
    int row  = blockIdx.x * 8 + (threadIdx.x >> 5);
    int lane = threadIdx.x & 31;
    int n = row / B_;
    int b = row - n * B_;
    const float4* u4  = (const float4*)(u  + (size_t)row * D_);
    const float4* x4  = (const float4*)(x  + (size_t)b   * D_);
    const float4* fl4 = (const float4*)(fl + n * D_);
    const float4* fw4 = (const float4*)(fw + n * D_);

    float s0 = 0.f, s1 = 0.f;
    #pragma unroll
    for (int i = 0; i < 8; i++) {
        int idx = i * 32 + lane;
        float4 uv = u4[idx], xv = x4[idx], flv = fl4[idx], fwv = fw4[idx];
        float e;
        e = __expf(flv.x - __logf(-__logf(uv.x + EPSF) + EPSF)); s0 += e; s1 += e * xv.x * fwv.x;
        e = __expf(flv.y - __logf(-__logf(uv.y + EPSF) + EPSF)); s0 += e; s1 += e * xv.y * fwv.y;
        e = __expf(flv.z - __logf(-__logf(uv.z + EPSF) + EPSF)); s0 += e; s1 += e * xv.z * fwv.z;
        e = __expf(flv.w - __logf(-__logf(uv.w + EPSF) + EPSF)); s0 += e; s1 += e * xv.w * fwv.w;
    }
    #pragma unroll
    for (int off = 16; off; off >>= 1) {
        s0 += __shfl_down_sync(0xffffffffu, s0, off);
        s1 += __shfl_down_sync(0xffffffffu, s1, off);
    }
    if (lane == 0) {
        float z = s1 / s0 - thr[n];
        g_split[row] = 1.f / (1.f + __expf(-z));
    }
}

// ============================================================
// Kernel 2: leaf routing probabilities
// ============================================================
__global__ void k_leaf_probs() {
    int b = blockIdx.x * blockDim.x + threadIdx.x;
    if (b >= B_) return;
    float s[NI];
    #pragma unroll
    for (int i = 0; i < NI; i++) s[i] = g_split[i * B_ + b];
    #pragma unroll
    for (int l = 0; l < NL; l++) {
        float p = 1.f;
        int pos = 0;
        #pragma unroll
        for (int k = 0; k < 4; k++) {
            int bit = (l >> (3 - k)) & 1;
            float sv = s[(1 << k) - 1 + pos];
            p *= bit ? sv : (1.f - sv);
            pos = 2 * pos + bit;
        }
        g_p[l * B_ + b] = p;
    }
}

// ============================================================
// Kernel 3: pack W2 [16][100][256] -> bf16 hi/lo [128 pad][4096]
// ============================================================
__global__ void k_pack_w2(const float* __restrict__ W2) {
    int idx = blockIdx.x * blockDim.x + threadIdx.x;
    if (idx >= 128 * HC) return;
    int c = idx / HC;
    int j = idx - c * HC;
    int l = j >> 8;
    int h = j & 255;
    float v = (c < NC) ? W2[((size_t)l * NC + c) * NH + h] : 0.f;
    __nv_bfloat16 hi = __float2bfloat16_rn(v);
    __nv_bfloat16 lo = __float2bfloat16_rn(v - __bfloat162float(hi));
    g_w2h[idx] = hi;
    g_w2l[idx] = lo;
}

// ============================================================
// shared HMMA mainloop machinery
// ============================================================
template<int LD>
__device__ __forceinline__ void stage_prefetch(uint32_t sbase, int stage,
                                               const __nv_bfloat16* Ah, const __nv_bfloat16* Al,
                                               const __nv_bfloat16* Bh, const __nv_bfloat16* Bl,
                                               int m0, int n0, int k0, int tid) {
    int r  = tid >> 1;              // 0..127
    int cs = (tid & 1) * 4;         // 0 or 4
    uint32_t st = sbase + stage * STAGE_BYTES;
    const __nv_bfloat16* srcs[4] = {
        Ah + (size_t)(m0 + r) * LD + k0,
        Al + (size_t)(m0 + r) * LD + k0,
        Bh + (size_t)(n0 + r) * LD + k0,
        Bl + (size_t)(n0 + r) * LD + k0
    };
    #pragma unroll
    for (int buf = 0; buf < 4; buf++) {
        uint32_t rowbase = st + buf * BUF_BYTES + r * 128;
        #pragma unroll
        for (int c = cs; c < cs + 4; c++) {
            uint32_t phys = (uint32_t)(c ^ (r & 7));
            cp_async16(rowbase + phys * 16, srcs[buf] + c * 8);
        }
    }
}

// G2=false: GEMM1  x@W1^T (K=1024) + relu/bias/p epilogue -> hs bf16 hi/lo
// G2=true : GEMM2  hs@W2cat^T (split-K over 8) -> fp32 partials
template<bool G2>
__global__ void __launch_bounds__(256, 1) k_gemm_tc(const float* __restrict__ b1) {
    extern __shared__ char smem[];
    uint32_t sbase = smem_to_u32(smem);
    int tid = threadIdx.x;
    int wid = tid >> 5, lane = tid & 31;
    int warp_m = wid & 1, warp_n = wid >> 1;
    int m_w = warp_m * 64, n_w = warp_n * 32;
    int m0 = blockIdx.y * TILE_M;

    constexpr int LD    = G2 ? HC : D_;
    constexpr int niter = G2 ? NITER2 : NITER1;
    const __nv_bfloat16* Ah = G2 ? g_hsh : g_xh;
    const __nv_bfloat16* Al = G2 ? g_hsl : g_xl;
    const __nv_bfloat16* Bh = G2 ? g_w2h : g_wh;
    const __nv_bfloat16* Bl = G2 ? g_w2l : g_wl;
    int n0    = G2 ? 0 : blockIdx.x * TILE_N;
    int kbase = G2 ? blockIdx.x * KCH2 : 0;

    float acc[4][4][4] = {};

    stage_prefetch<LD>(sbase, 0, Ah, Al, Bh, Bl, m0, n0, kbase, tid);
    cp_commit();
    stage_prefetch<LD>(sbase, 1, Ah, Al, Bh, Bl, m0, n0, kbase + KCHUNK, tid);
    cp_commit();
    stage_prefetch<LD>(sbase, 2, Ah, Al, Bh, Bl, m0, n0, kbase + 2 * KCHUNK, tid);
    cp_commit();

    for (int i = 0; i < niter; i++) {
        int s = i % NSTAGE;
        cp_wait<2>();
        __syncthreads();

        uint32_t st = sbase + s * STAGE_BYTES;
        #pragma unroll
        for (int kk = 0; kk < 4; kk++) {
            int cbase = kk * 2;
            uint32_t ah[4][4], al[4][4], bh[4][2], bl[4][2];
            #pragma unroll
            for (int mi = 0; mi < 4; mi++) {
                int r = m_w + mi * 16 + (lane & 15);
                uint32_t ch = (uint32_t)((cbase + (lane >> 4)) ^ (r & 7));
                uint32_t off = (uint32_t)r * 128 + ch * 16;
                ldm_x4(ah[mi][0], ah[mi][1], ah[mi][2], ah[mi][3], st + off);
                ldm_x4(al[mi][0], al[mi][1], al[mi][2], al[mi][3], st + BUF_BYTES + off);
            }
            // B: one x4 covers (ni, ni+1) x (k-chunk 0,1)
            #pragma unroll
            for (int nip = 0; nip < 2; nip++) {
                int g = lane >> 3;                                  // 0..3
                int r = n_w + (nip * 2 + (g >> 1)) * 8 + (lane & 7);
                uint32_t ch = (uint32_t)((cbase + (g & 1)) ^ (r & 7));
                uint32_t off = (uint32_t)r * 128 + ch * 16;
                ldm_x4(bh[nip*2][0], bh[nip*2][1], bh[nip*2+1][0], bh[nip*2+1][1],
                       st + 2 * BUF_BYTES + off);
                ldm_x4(bl[nip*2][0], bl[nip*2][1], bl[nip*2+1][0], bl[nip*2+1][1],
                       st + 3 * BUF_BYTES + off);
            }
            #pragma unroll
            for (int mi = 0; mi < 4; mi++)
                #pragma unroll
                for (int ni = 0; ni < 4; ni++) {
                    mma_bf16(acc[mi][ni], ah[mi], bh[ni]);
                    mma_bf16(acc[mi][ni], ah[mi], bl[ni]);
                    mma_bf16(acc[mi][ni], al[mi], bh[ni]);
                }
        }
        __syncthreads();
        if (i + NSTAGE < niter)
            stage_prefetch<LD>(sbase, s, Ah, Al, Bh, Bl, m0, n0, kbase + (i + NSTAGE) * KCHUNK, tid);
        cp_commit();
    }

    int trow = lane >> 2;
    int tcol = (lane & 3) * 2;
    if (!G2) {
        int leaf = n0 >> 8;
        #pragma unroll
        for (int mi = 0; mi < 4; mi++) {
            int mA = m0 + m_w + mi * 16 + trow;
            int mB = mA + 8;
            float pA = g_p[leaf * B_ + mA];
            float pB = g_p[leaf * B_ + mB];
            #pragma unroll
            for (int ni = 0; ni < 4; ni++) {
                int n = n0 + n_w + ni * 8 + tcol;
                float bv0 = __ldg(&b1[n]), bv1 = __ldg(&b1[n + 1]);
                float v00 = fmaxf(acc[mi][ni][0] + bv0, 0.f) * pA;
                float v01 = fmaxf(acc[mi][ni][1] + bv1, 0.f) * pA;
                float v10 = fmaxf(acc[mi][ni][2] + bv0, 0.f) * pB;
                float v11 = fmaxf(acc[mi][ni][3] + bv1, 0.f) * pB;
                __nv_bfloat16 h00 = __float2bfloat16_rn(v00);
                __nv_bfloat16 h01 = __float2bfloat16_rn(v01);
                __nv_bfloat16 h10 = __float2bfloat16_rn(v10);
                __nv_bfloat16 h11 = __float2bfloat16_rn(v11);
                __nv_bfloat16 l00 = __float2bfloat16_rn(v00 - __bfloat162float(h00));
                __nv_bfloat16 l01 = __float2bfloat16_rn(v01 - __bfloat162float(h01));
                __nv_bfloat16 l10 = __float2bfloat16_rn(v10 - __bfloat162float(h10));
                __nv_bfloat16 l11 = __float2bfloat16_rn(v11 - __bfloat162float(h11));
                size_t iA = (size_t)mA * HC + n, iB = (size_t)mB * HC + n;
                *(__nv_bfloat162*)&g_hsh[iA] = __nv_bfloat162(h00, h01);
                *(__nv_bfloat162*)&g_hsl[iA] = __nv_bfloat162(l00, l01);
                *(__nv_bfloat162*)&g_hsh[iB] = __nv_bfloat162(h10, h11);
                *(__nv_bfloat162*)&g_hsl[iB] = __nv_bfloat162(l10, l11);
            }
        }
    } else {
        float* part = g_part[blockIdx.x];
        #pragma unroll
        for (int mi = 0; mi < 4; mi++) {
            int mA = m0 + m_w + mi * 16 + trow;
            int mB = mA + 8;
            #pragma unroll
            for (int ni = 0; ni < 4; ni++) {
                int n = n_w + ni * 8 + tcol;
                *(float2*)&part[(size_t)mA * 128 + n] = make_float2(acc[mi][ni][0], acc[mi][ni][1]);
                *(float2*)&part[(size_t)mB * 128 + n] = make_float2(acc[mi][ni][2], acc[mi][ni][3]);
            }
        }
    }
}

// ============================================================
// Kernel 6: reduce split-K + leaf-weighted b2
// ============================================================
__global__ void k_reduce(const float* __restrict__ b2, float* __restrict__ out) {
    int idx = blockIdx.x * blockDim.x + threadIdx.x;
    if (idx >= B_ * NC) return;
    int b = idx / NC;
    int c = idx - b * NC;
    float v = 0.f;
    #pragma unroll
    for (int s = 0; s < KSPLIT2; s++) v += g_part[s][(size_t)b * 128 + c];
    float bias = 0.f;
    #pragma unroll
    for (int l = 0; l < NL; l++) bias += g_p[l * B_ + b] * b2[l * NC + c];
    out[idx] = v + bias;
}

extern "C" void kernel_launch(void* const* d_in, const int* in_sizes, int n_in,
                              void* d_out, int out_size) {
    const float* x   = (const float*)d_in[0];
    const float* u   = (const float*)d_in[1];
    const float* fl  = (const float*)d_in[2];
    const float* thr = (const float*)d_in[3];
    const float* fw  = (const float*)d_in[4];
    const float* W1  = (const float*)d_in[5];
    const float* b1  = (const float*)d_in[6];
    const float* W2  = (const float*)d_in[7];
    const float* b2  = (const float*)d_in[8];
    float* out = (float*)d_out;

    cudaFuncSetAttribute(k_gemm_tc<false>, cudaFuncAttributeMaxDynamicSharedMemorySize, SMEM_TOTAL);
    cudaFuncSetAttribute(k_gemm_tc<true>,  cudaFuncAttributeMaxDynamicSharedMemorySize, SMEM_TOTAL);

    // launch order chosen so k_gemm_tc<false> is launch #3 (profiled slot)
    k_split_all<<<(N4X + N4W + 255) / 256, 256>>>(x, W1);
    k_gumbel_split<<<NI * B_ / 8, 256>>>(x, u, fl, thr, fw);
    k_leaf_probs<<<B_ / 256, 256>>>();
    k_gemm_tc<false><<<dim3(HC / TILE_N, B_ / TILE_M), 256, SMEM_TOTAL>>>(b1);
    k_pack_w2<<<(128 * HC + 255) / 256, 256>>>(W2);
    k_gemm_tc<true><<<dim3(KSPLIT2, B_ / TILE_M), 256, SMEM_TOTAL>>>(nullptr);
    k_reduce<<<(B_ * NC + 255) / 256, 256>>>(b2, out);
}

// round 6
// speedup vs baseline: 2.5163x; 1.0060x over previous
#include <cuda_runtime.h>
#include <cuda_bf16.h>
#include <cstdint>

#define B_    4096
#define D_    1024
#define NI    15
#define NL    16
#define NH    256
#define NC    100
#define HC    4096
#define EPSF  1e-10f

// GEMM tiling (HMMA path): 128(M) x 64(N) x 64(K-stage), 2 stages, 2 CTAs/SM
#define TILE_M 128
#define TILE_N 64
#define KCHUNK 64
#define NITER1 (D_ / KCHUNK)            // 16 (GEMM1)
#define KSPLIT2 8
#define KCH2   (HC / KSPLIT2)           // 512
#define NITER2 (KCH2 / KCHUNK)          // 8 (GEMM2)
#define ABUF   (TILE_M * 128)           // 16KB per A operand
#define BBUF   (TILE_N * 128)           // 8KB per B operand
#define STAGE_BYTES (2*ABUF + 2*BBUF)   // 48KB
#define NSTAGE 2
#define SMEM_TOTAL (NSTAGE * STAGE_BYTES) // 96KB -> 2 CTAs/SM

// ---- scratch (device globals) ----
__device__ float g_split[NI * B_];
__device__ float g_p[NL * B_];
__device__ float g_part[KSPLIT2][(size_t)B_ * 128];
__device__ __nv_bfloat16 g_xh[(size_t)B_ * D_];
__device__ __nv_bfloat16 g_xl[(size_t)B_ * D_];
__device__ __nv_bfloat16 g_wh[(size_t)HC * D_];
__device__ __nv_bfloat16 g_wl[(size_t)HC * D_];
__device__ __nv_bfloat16 g_hsh[(size_t)B_ * HC];
__device__ __nv_bfloat16 g_hsl[(size_t)B_ * HC];
__device__ __nv_bfloat16 g_w2h[(size_t)128 * HC];
__device__ __nv_bfloat16 g_w2l[(size_t)128 * HC];

// ============================================================
// helpers
// ============================================================
__device__ __forceinline__ uint32_t smem_to_u32(const void* p) {
    uint32_t a;
    asm("{ .reg .u64 t; cvta.to.shared.u64 t, %1; cvt.u32.u64 %0, t; }" : "=r"(a) : "l"(p));
    return a;
}
__device__ __forceinline__ void cp_async16(uint32_t dst, const void* src) {
    asm volatile("cp.async.cg.shared.global [%0], [%1], 16;" :: "r"(dst), "l"(src));
}
__device__ __forceinline__ void cp_commit() { asm volatile("cp.async.commit_group;"); }
template<int N> __device__ __forceinline__ void cp_wait() {
    asm volatile("cp.async.wait_group %0;" :: "n"(N));
}
__device__ __forceinline__ void ldm_x4(uint32_t& r0, uint32_t& r1, uint32_t& r2, uint32_t& r3, uint32_t addr) {
    asm volatile("ldmatrix.sync.aligned.m8n8.x4.shared.b16 {%0,%1,%2,%3}, [%4];"
                 : "=r"(r0), "=r"(r1), "=r"(r2), "=r"(r3) : "r"(addr));
}
__device__ __forceinline__ void mma_bf16(float* d, const uint32_t* a, const uint32_t* b) {
    asm volatile("mma.sync.aligned.m16n8k16.row.col.f32.bf16.bf16.f32 "
                 "{%0,%1,%2,%3}, {%4,%5,%6,%7}, {%8,%9}, {%0,%1,%2,%3};"
                 : "+f"(d[0]), "+f"(d[1]), "+f"(d[2]), "+f"(d[3])
                 : "r"(a[0]), "r"(a[1]), "r"(a[2]), "r"(a[3]), "r"(b[0]), "r"(b[1]));
}

// ============================================================
// Kernel 0: fp32 -> bf16 hi/lo split for BOTH x and W1
// ============================================================
#define N4X (B_ * D_ / 4)
#define N4W (HC * D_ / 4)
__global__ void k_split_all(const float* __restrict__ x, const float* __restrict__ w) {
    int i = blockIdx.x * blockDim.x + threadIdx.x;
    const float* s;
    __nv_bfloat16 *hi, *lo;
    int j;
    if (i < N4X) { s = x; hi = g_xh; lo = g_xl; j = i; }
    else if (i < N4X + N4W) { s = w; hi = g_wh; lo = g_wl; j = i - N4X; }
    else return;
    float4 v = ((const float4*)s)[j];
    __nv_bfloat16 h0 = __float2bfloat16_rn(v.x), h1 = __float2bfloat16_rn(v.y);
    __nv_bfloat16 h2 = __float2bfloat16_rn(v.z), h3 = __float2bfloat16_rn(v.w);
    __nv_bfloat16 l0 = __float2bfloat16_rn(v.x - __bfloat162float(h0));
    __nv_bfloat16 l1 = __float2bfloat16_rn(v.y - __bfloat162float(h1));
    __nv_bfloat16 l2 = __float2bfloat16_rn(v.z - __bfloat162float(h2));
    __nv_bfloat16 l3 = __float2bfloat16_rn(v.w - __bfloat162float(h3));
    ((__nv_bfloat162*)hi)[2*j]   = __nv_bfloat162(h0, h1);
    ((__nv_bfloat162*)hi)[2*j+1] = __nv_bfloat162(h2, h3);
    ((__nv_bfloat162*)lo)[2*j]   = __nv_bfloat162(l0, l1);
    ((__nv_bfloat162*)lo)[2*j+1] = __nv_bfloat162(l2, l3);
}

// ============================================================
// Kernel 1: gumbel gate + split sigmoid (warp per row)
// ============================================================
__global__ void k_gumbel_split(const float* __restrict__ x,
                               const float* __restrict__ u,
                               const float* __restrict__ fl,
                               const float* __restrict__ thr,
                               const float* __restrict__ fw) {
    int row  = blockIdx.x * 8 + (threadIdx.x >> 5);
    int lane = threadIdx.x & 31;
    int n = row / B_;
    int b = row - n * B_;
    const float4* u4  = (const float4*)(u  + (size_t)row * D_);
    const float4* x4  = (const float4*)(x  + (size_t)b   * D_);
    const float4* fl4 = (const float4*)(fl + n * D_);
    const float4* fw4 = (const float4*)(fw + n * D_);

    float s0 = 0.f, s1 = 0.f;
    #pragma unroll
    for (int i = 0; i < 8; i++) {
        int idx = i * 32 + lane;
        float4 uv = u4[idx], xv = x4[idx], flv = fl4[idx], fwv = fw4[idx];
        float e;
        e = __expf(flv.x - __logf(-__logf(uv.x + EPSF) + EPSF)); s0 += e; s1 += e * xv.x * fwv.x;
        e = __expf(flv.y - __logf(-__logf(uv.y + EPSF) + EPSF)); s0 += e; s1 += e * xv.y * fwv.y;
        e = __expf(flv.z - __logf(-__logf(uv.z + EPSF) + EPSF)); s0 += e; s1 += e * xv.z * fwv.z;
        e = __expf(flv.w - __logf(-__logf(uv.w + EPSF) + EPSF)); s0 += e; s1 += e * xv.w * fwv.w;
    }
    #pragma unroll
    for (int off = 16; off; off >>= 1) {
        s0 += __shfl_down_sync(0xffffffffu, s0, off);
        s1 += __shfl_down_sync(0xffffffffu, s1, off);
    }
    if (lane == 0) {
        float z = s1 / s0 - thr[n];
        g_split[row] = 1.f / (1.f + __expf(-z));
    }
}

// ============================================================
// Kernel 2: leaf routing probabilities
// ============================================================
__global__ void k_leaf_probs() {
    int b = blockIdx.x * blockDim.x + threadIdx.x;
    if (b >= B_) return;
    float s[NI];
    #pragma unroll
    for (int i = 0; i < NI; i++) s[i] = g_split[i * B_ + b];
    #pragma unroll
    for (int l = 0; l < NL; l++) {
        float p = 1.f;
        int pos = 0;
        #pragma unroll
        for (int k = 0; k < 4; k++) {
            int bit = (l >> (3 - k)) & 1;
            float sv = s[(1 << k) - 1 + pos];
            p *= bit ? sv : (1.f - sv);
            pos = 2 * pos + bit;
        }
        g_p[l * B_ + b] = p;
    }
}

// ============================================================
// Kernel 3: pack W2 [16][100][256] -> bf16 hi/lo [128 pad][4096]
// ============================================================
__global__ void k_pack_w2(const float* __restrict__ W2) {
    int idx = blockIdx.x * blockDim.x + threadIdx.x;
    if (idx >= 128 * HC) return;
    int c = idx / HC;
    int j = idx - c * HC;
    int l = j >> 8;
    int h = j & 255;
    float v = (c < NC) ? W2[((size_t)l * NC + c) * NH + h] : 0.f;
    __nv_bfloat16 hi = __float2bfloat16_rn(v);
    __nv_bfloat16 lo = __float2bfloat16_rn(v - __bfloat162float(hi));
    g_w2h[idx] = hi;
    g_w2l[idx] = lo;
}

// ============================================================
// shared HMMA mainloop machinery (128x64 tile)
// ============================================================
template<int LD>
__device__ __forceinline__ void stage_prefetch(uint32_t sbase, int stage,
                                               const __nv_bfloat16* Ah, const __nv_bfloat16* Al,
                                               const __nv_bfloat16* Bh, const __nv_bfloat16* Bl,
                                               int m0, int n0, int k0, int tid) {
    uint32_t st = sbase + stage * STAGE_BYTES;
    // A bufs: 128 rows, 2 threads/row -> 4 cp16 each
    {
        int r  = tid >> 1;
        int cs = (tid & 1) * 4;
        const __nv_bfloat16* sa_h = Ah + (size_t)(m0 + r) * LD + k0;
        const __nv_bfloat16* sa_l = Al + (size_t)(m0 + r) * LD + k0;
        uint32_t rb_h = st + r * 128;
        uint32_t rb_l = st + ABUF + r * 128;
        #pragma unroll
        for (int c = cs; c < cs + 4; c++) {
            uint32_t phys = (uint32_t)(c ^ (r & 7)) * 16;
            cp_async16(rb_h + phys, sa_h + c * 8);
            cp_async16(rb_l + phys, sa_l + c * 8);
        }
    }
    // B bufs: 64 rows, 4 threads/row -> 2 cp16 each
    {
        int r  = tid >> 2;
        int cs = (tid & 3) * 2;
        const __nv_bfloat16* sb_h = Bh + (size_t)(n0 + r) * LD + k0;
        const __nv_bfloat16* sb_l = Bl + (size_t)(n0 + r) * LD + k0;
        uint32_t rb_h = st + 2 * ABUF + r * 128;
        uint32_t rb_l = st + 2 * ABUF + BBUF + r * 128;
        #pragma unroll
        for (int c = cs; c < cs + 2; c++) {
            uint32_t phys = (uint32_t)(c ^ (r & 7)) * 16;
            cp_async16(rb_h + phys, sb_h + c * 8);
            cp_async16(rb_l + phys, sb_l + c * 8);
        }
    }
}

// G2=false: GEMM1  x@W1^T (K=1024) + relu/bias/p epilogue -> hs bf16 hi/lo
// G2=true : GEMM2  hs@W2cat^T (split-K over 8) -> fp32 partials
template<bool G2>
__global__ void __launch_bounds__(256, 2) k_gemm_tc(const float* __restrict__ b1) {
    extern __shared__ char smem[];
    uint32_t sbase = smem_to_u32(smem);
    int tid = threadIdx.x;
    int wid = tid >> 5, lane = tid & 31;
    int m_w = (wid & 3) * 32;           // 4 warps over M (32 rows each)
    int n_w = (wid >> 2) * 32;          // 2 warps over N (32 cols each)
    int m0 = blockIdx.y * TILE_M;

    constexpr int LD    = G2 ? HC : D_;
    constexpr int niter = G2 ? NITER2 : NITER1;
    const __nv_bfloat16* Ah = G2 ? g_hsh : g_xh;
    const __nv_bfloat16* Al = G2 ? g_hsl : g_xl;
    const __nv_bfloat16* Bh = G2 ? g_w2h : g_wh;
    const __nv_bfloat16* Bl = G2 ? g_w2l : g_wl;
    int n0    = G2 ? (blockIdx.x & 1) * TILE_N : blockIdx.x * TILE_N;
    int kbase = G2 ? (blockIdx.x >> 1) * KCH2 : 0;

    float acc[2][4][4] = {};

    stage_prefetch<LD>(sbase, 0, Ah, Al, Bh, Bl, m0, n0, kbase, tid);
    cp_commit();
    stage_prefetch<LD>(sbase, 1, Ah, Al, Bh, Bl, m0, n0, kbase + KCHUNK, tid);
    cp_commit();

    for (int i = 0; i < niter; i++) {
        int s = i & 1;
        cp_wait<1>();
        __syncthreads();

        uint32_t st = sbase + s * STAGE_BYTES;
        #pragma unroll
        for (int kk = 0; kk < 4; kk++) {
            int cbase = kk * 2;
            uint32_t ah[2][4], al[2][4], bh[4][2], bl[4][2];
            #pragma unroll
            for (int mi = 0; mi < 2; mi++) {
                int r = m_w + mi * 16 + (lane & 15);
                uint32_t ch = (uint32_t)((cbase + (lane >> 4)) ^ (r & 7));
                uint32_t off = (uint32_t)r * 128 + ch * 16;
                ldm_x4(ah[mi][0], ah[mi][1], ah[mi][2], ah[mi][3], st + off);
                ldm_x4(al[mi][0], al[mi][1], al[mi][2], al[mi][3], st + ABUF + off);
            }
            // B: one x4 covers (ni, ni+1) x (k-chunk 0,1)
            #pragma unroll
            for (int nip = 0; nip < 2; nip++) {
                int g = lane >> 3;
                int r = n_w + (nip * 2 + (g >> 1)) * 8 + (lane & 7);
                uint32_t ch = (uint32_t)((cbase + (g & 1)) ^ (r & 7));
                uint32_t off = (uint32_t)r * 128 + ch * 16;
                ldm_x4(bh[nip*2][0], bh[nip*2][1], bh[nip*2+1][0], bh[nip*2+1][1],
                       st + 2 * ABUF + off);
                ldm_x4(bl[nip*2][0], bl[nip*2][1], bl[nip*2+1][0], bl[nip*2+1][1],
                       st + 2 * ABUF + BBUF + off);
            }
            #pragma unroll
            for (int mi = 0; mi < 2; mi++)
                #pragma unroll
                for (int ni = 0; ni < 4; ni++) {
                    mma_bf16(acc[mi][ni], ah[mi], bh[ni]);
                    mma_bf16(acc[mi][ni], ah[mi], bl[ni]);
                    mma_bf16(acc[mi][ni], al[mi], bh[ni]);
                }
        }
        __syncthreads();
        if (i + NSTAGE < niter)
            stage_prefetch<LD>(sbase, s, Ah, Al, Bh, Bl, m0, n0, kbase + (i + NSTAGE) * KCHUNK, tid);
        cp_commit();
    }

    int trow = lane >> 2;
    int tcol = (lane & 3) * 2;
    if (!G2) {
        int leaf = n0 >> 8;
        #pragma unroll
        for (int mi = 0; mi < 2; mi++) {
            int mA = m0 + m_w + mi * 16 + trow;
            int mB = mA + 8;
            float pA = g_p[leaf * B_ + mA];
            float pB = g_p[leaf * B_ + mB];
            #pragma unroll
            for (int ni = 0; ni < 4; ni++) {
                int n = n0 + n_w + ni * 8 + tcol;
                float bv0 = __ldg(&b1[n]), bv1 = __ldg(&b1[n + 1]);
                float v00 = fmaxf(acc[mi][ni][0] + bv0, 0.f) * pA;
                float v01 = fmaxf(acc[mi][ni][1] + bv1, 0.f) * pA;
                float v10 = fmaxf(acc[mi][ni][2] + bv0, 0.f) * pB;
                float v11 = fmaxf(acc[mi][ni][3] + bv1, 0.f) * pB;
                __nv_bfloat16 h00 = __float2bfloat16_rn(v00);
                __nv_bfloat16 h01 = __float2bfloat16_rn(v01);
                __nv_bfloat16 h10 = __float2bfloat16_rn(v10);
                __nv_bfloat16 h11 = __float2bfloat16_rn(v11);
                __nv_bfloat16 l00 = __float2bfloat16_rn(v00 - __bfloat162float(h00));
                __nv_bfloat16 l01 = __float2bfloat16_rn(v01 - __bfloat162float(h01));
                __nv_bfloat16 l10 = __float2bfloat16_rn(v10 - __bfloat162float(h10));
                __nv_bfloat16 l11 = __float2bfloat16_rn(v11 - __bfloat162float(h11));
                size_t iA = (size_t)mA * HC + n, iB = (size_t)mB * HC + n;
                *(__nv_bfloat162*)&g_hsh[iA] = __nv_bfloat162(h00, h01);
                *(__nv_bfloat162*)&g_hsl[iA] = __nv_bfloat162(l00, l01);
                *(__nv_bfloat162*)&g_hsh[iB] = __nv_bfloat162(h10, h11);
                *(__nv_bfloat162*)&g_hsl[iB] = __nv_bfloat162(l10, l11);
            }
        }
    } else {
        float* part = g_part[blockIdx.x >> 1];
        #pragma unroll
        for (int mi = 0; mi < 2; mi++) {
            int mA = m0 + m_w + mi * 16 + trow;
            int mB = mA + 8;
            #pragma unroll
            for (int ni = 0; ni < 4; ni++) {
                int n = n0 + n_w + ni * 8 + tcol;
                *(float2*)&part[(size_t)mA * 128 + n] = make_float2(acc[mi][ni][0], acc[mi][ni][1]);
                *(float2*)&part[(size_t)mB * 128 + n] = make_float2(acc[mi][ni][2], acc[mi][ni][3]);
            }
        }
    }
}

// ============================================================
// Kernel 6: reduce split-K + leaf-weighted b2
// ============================================================
__global__ void k_reduce(const float* __restrict__ b2, float* __restrict__ out) {
    int idx = blockIdx.x * blockDim.x + threadIdx.x;
    if (idx >= B_ * NC) return;
    int b = idx / NC;
    int c = idx - b * NC;
    float v = 0.f;
    #pragma unroll
    for (int s = 0; s < KSPLIT2; s++) v += g_part[s][(size_t)b * 128 + c];
    float bias = 0.f;
    #pragma unroll
    for (int l = 0; l < NL; l++) bias += g_p[l * B_ + b] * b2[l * NC + c];
    out[idx] = v + bias;
}

extern "C" void kernel_launch(void* const* d_in, const int* in_sizes, int n_in,
                              void* d_out, int out_size) {
    const float* x   = (const float*)d_in[0];
    const float* u   = (const float*)d_in[1];
    const float* fl  = (const float*)d_in[2];
    const float* thr = (const float*)d_in[3];
    const float* fw  = (const float*)d_in[4];
    const float* W1  = (const float*)d_in[5];
    const float* b1  = (const float*)d_in[6];
    const float* W2  = (const float*)d_in[7];
    const float* b2  = (const float*)d_in[8];
    float* out = (float*)d_out;

    cudaFuncSetAttribute(k_gemm_tc<false>, cudaFuncAttributeMaxDynamicSharedMemorySize, SMEM_TOTAL);
    cudaFuncSetAttribute(k_gemm_tc<true>,  cudaFuncAttributeMaxDynamicSharedMemorySize, SMEM_TOTAL);

    // launch order: k_gemm_tc<false> stays launch #3 (profiled slot)
    k_split_all<<<(N4X + N4W + 255) / 256, 256>>>(x, W1);
    k_gumbel_split<<<NI * B_ / 8, 256>>>(x, u, fl, thr, fw);
    k_leaf_probs<<<B_ / 256, 256>>>();
    k_gemm_tc<false><<<dim3(HC / TILE_N, B_ / TILE_M), 256, SMEM_TOTAL>>>(b1);
    k_pack_w2<<<(128 * HC + 255) / 256, 256>>>(W2);
    k_gemm_tc<true><<<dim3(KSPLIT2 * 2, B_ / TILE_M), 256, SMEM_TOTAL>>>(nullptr);
    k_reduce<<<(B_ * NC + 255) / 256, 256>>>(b2, out);
}

// round 7
// speedup vs baseline: 3.1088x; 1.2355x over previous
#include <cuda_runtime.h>
#include <cuda_fp16.h>
#include <cstdint>

#define B_    4096
#define D_    1024
#define NI    15
#define NL    16
#define NH    256
#define NC    100
#define HC    4096
#define EPSF  1e-10f

// GEMM tiling: 128(M) x 64(N) x 64(K-stage), 2 stages, 2 CTAs/SM
#define TILE_M 128
#define TILE_N 64
#define KCHUNK 64
#define NITER1 (D_ / KCHUNK)            // 16 (GEMM1)
#define KSPLIT2 8
#define KCH2   (HC / KSPLIT2)           // 512
#define NITER2 (KCH2 / KCHUNK)          // 8 (GEMM2)
#define ABUF   (TILE_M * 128)           // 16KB per A operand
#define BBUF   (TILE_N * 128)           // 8KB for B
#define STAGE_BYTES (2*ABUF + BBUF)     // 40KB
#define NSTAGE 2
#define SMEM_TOTAL (NSTAGE * STAGE_BYTES) // 80KB -> 2 CTAs/SM

// ---- scratch (device globals) ----
__device__ float g_split[NI * B_];
__device__ float g_p[NL * B_];
__device__ float g_part[KSPLIT2][(size_t)B_ * 128];
__device__ __half g_xh[(size_t)B_ * D_];
__device__ __half g_xl[(size_t)B_ * D_];
__device__ __half g_wh[(size_t)HC * D_];
__device__ __half g_hsh[(size_t)B_ * HC];
__device__ __half g_hsl[(size_t)B_ * HC];
__device__ __half g_w2h[(size_t)128 * HC];

// ============================================================
// helpers
// ============================================================
__device__ __forceinline__ uint32_t smem_to_u32(const void* p) {
    uint32_t a;
    asm("{ .reg .u64 t; cvta.to.shared.u64 t, %1; cvt.u32.u64 %0, t; }" : "=r"(a) : "l"(p));
    return a;
}
__device__ __forceinline__ void cp_async16(uint32_t dst, const void* src) {
    asm volatile("cp.async.cg.shared.global [%0], [%1], 16;" :: "r"(dst), "l"(src));
}
__device__ __forceinline__ void cp_commit() { asm volatile("cp.async.commit_group;"); }
template<int N> __device__ __forceinline__ void cp_wait() {
    asm volatile("cp.async.wait_group %0;" :: "n"(N));
}
__device__ __forceinline__ void ldm_x4(uint32_t& r0, uint32_t& r1, uint32_t& r2, uint32_t& r3, uint32_t addr) {
    asm volatile("ldmatrix.sync.aligned.m8n8.x4.shared.b16 {%0,%1,%2,%3}, [%4];"
                 : "=r"(r0), "=r"(r1), "=r"(r2), "=r"(r3) : "r"(addr));
}
__device__ __forceinline__ void mma_fp16(float* d, const uint32_t* a, const uint32_t* b) {
    asm volatile("mma.sync.aligned.m16n8k16.row.col.f32.f16.f16.f32 "
                 "{%0,%1,%2,%3}, {%4,%5,%6,%7}, {%8,%9}, {%0,%1,%2,%3};"
                 : "+f"(d[0]), "+f"(d[1]), "+f"(d[2]), "+f"(d[3])
                 : "r"(a[0]), "r"(a[1]), "r"(a[2]), "r"(a[3]), "r"(b[0]), "r"(b[1]));
}

// ============================================================
// Kernel 0: fp32 -> fp16 conversions: x -> hi/lo, W1 -> single
// ============================================================
#define N4X (B_ * D_ / 4)
#define N4W (HC * D_ / 4)
__global__ void k_split_all(const float* __restrict__ x, const float* __restrict__ w) {
    int i = blockIdx.x * blockDim.x + threadIdx.x;
    if (i < N4X) {
        float4 v = ((const float4*)x)[i];
        __half h0 = __float2half_rn(v.x), h1 = __float2half_rn(v.y);
        __half h2 = __float2half_rn(v.z), h3 = __float2half_rn(v.w);
        __half l0 = __float2half_rn(v.x - __half2float(h0));
        __half l1 = __float2half_rn(v.y - __half2float(h1));
        __half l2 = __float2half_rn(v.z - __half2float(h2));
        __half l3 = __float2half_rn(v.w - __half2float(h3));
        ((__half2*)g_xh)[2*i]   = __half2(h0, h1);
        ((__half2*)g_xh)[2*i+1] = __half2(h2, h3);
        ((__half2*)g_xl)[2*i]   = __half2(l0, l1);
        ((__half2*)g_xl)[2*i+1] = __half2(l2, l3);
    } else if (i < N4X + N4W) {
        int j = i - N4X;
        float4 v = ((const float4*)w)[j];
        ((__half2*)g_wh)[2*j]   = __half2(__float2half_rn(v.x), __float2half_rn(v.y));
        ((__half2*)g_wh)[2*j+1] = __half2(__float2half_rn(v.z), __float2half_rn(v.w));
    }
}

// ============================================================
// Kernel 1: gumbel gate + split sigmoid (warp per row)
// ============================================================
__global__ void k_gumbel_split(const float* __restrict__ x,
                               const float* __restrict__ u,
                               const float* __restrict__ fl,
                               const float* __restrict__ thr,
                               const float* __restrict__ fw) {
    int row  = blockIdx.x * 8 + (threadIdx.x >> 5);
    int lane = threadIdx.x & 31;
    int n = row / B_;
    int b = row - n * B_;
    const float4* u4  = (const float4*)(u  + (size_t)row * D_);
    const float4* x4  = (const float4*)(x  + (size_t)b   * D_);
    const float4* fl4 = (const float4*)(fl + n * D_);
    const float4* fw4 = (const float4*)(fw + n * D_);

    float s0 = 0.f, s1 = 0.f;
    #pragma unroll
    for (int i = 0; i < 8; i++) {
        int idx = i * 32 + lane;
        float4 uv = u4[idx], xv = x4[idx], flv = fl4[idx], fwv = fw4[idx];
        float e;
        e = __expf(flv.x - __logf(-__logf(uv.x + EPSF) + EPSF)); s0 += e; s1 += e * xv.x * fwv.x;
        e = __expf(flv.y - __logf(-__logf(uv.y + EPSF) + EPSF)); s0 += e; s1 += e * xv.y * fwv.y;
        e = __expf(flv.z - __logf(-__logf(uv.z + EPSF) + EPSF)); s0 += e; s1 += e * xv.z * fwv.z;
        e = __expf(flv.w - __logf(-__logf(uv.w + EPSF) + EPSF)); s0 += e; s1 += e * xv.w * fwv.w;
    }
    #pragma unroll
    for (int off = 16; off; off >>= 1) {
        s0 += __shfl_down_sync(0xffffffffu, s0, off);
        s1 += __shfl_down_sync(0xffffffffu, s1, off);
    }
    if (lane == 0) {
        float z = s1 / s0 - thr[n];
        g_split[row] = 1.f / (1.f + __expf(-z));
    }
}

// ============================================================
// Kernel 2: leaf routing probabilities
// ============================================================
__global__ void k_leaf_probs() {
    int b = blockIdx.x * blockDim.x + threadIdx.x;
    if (b >= B_) return;
    float s[NI];
    #pragma unroll
    for (int i = 0; i < NI; i++) s[i] = g_split[i * B_ + b];
    #pragma unroll
    for (int l = 0; l < NL; l++) {
        float p = 1.f;
        int pos = 0;
        #pragma unroll
        for (int k = 0; k < 4; k++) {
            int bit = (l >> (3 - k)) & 1;
            float sv = s[(1 << k) - 1 + pos];
            p *= bit ? sv : (1.f - sv);
            pos = 2 * pos + bit;
        }
        g_p[l * B_ + b] = p;
    }
}

// ============================================================
// Kernel 3: pack W2 [16][100][256] -> fp16 [128 pad][4096]
// ============================================================
__global__ void k_pack_w2(const float* __restrict__ W2) {
    int idx = blockIdx.x * blockDim.x + threadIdx.x;
    if (idx >= 128 * HC) return;
    int c = idx / HC;
    int j = idx - c * HC;
    int l = j >> 8;
    int h = j & 255;
    float v = (c < NC) ? W2[((size_t)l * NC + c) * NH + h] : 0.f;
    g_w2h[idx] = __float2half_rn(v);
}

// ============================================================
// shared HMMA mainloop (128x64 tile, fp16 2-term, frag pipelined)
// ============================================================
template<int LD>
__device__ __forceinline__ void stage_prefetch(uint32_t sbase, int stage,
                                               const __half* Ah, const __half* Al,
                                               const __half* Bh,
                                               int m0, int n0, int k0, int tid) {
    uint32_t st = sbase + stage * STAGE_BYTES;
    // A bufs: 128 rows, 2 threads/row -> 4 cp16 each (hi and lo)
    {
        int r  = tid >> 1;
        int cs = (tid & 1) * 4;
        const __half* sa_h = Ah + (size_t)(m0 + r) * LD + k0;
        const __half* sa_l = Al + (size_t)(m0 + r) * LD + k0;
        uint32_t rb_h = st + r * 128;
        uint32_t rb_l = st + ABUF + r * 128;
        #pragma unroll
        for (int c = cs; c < cs + 4; c++) {
            uint32_t phys = (uint32_t)(c ^ (r & 7)) * 16;
            cp_async16(rb_h + phys, sa_h + c * 8);
            cp_async16(rb_l + phys, sa_l + c * 8);
        }
    }
    // B buf: 64 rows, 4 threads/row -> 2 cp16 each
    {
        int r  = tid >> 2;
        int cs = (tid & 3) * 2;
        const __half* sb_h = Bh + (size_t)(n0 + r) * LD + k0;
        uint32_t rb_h = st + 2 * ABUF + r * 128;
        #pragma unroll
        for (int c = cs; c < cs + 2; c++) {
            uint32_t phys = (uint32_t)(c ^ (r & 7)) * 16;
            cp_async16(rb_h + phys, sb_h + c * 8);
        }
    }
}

// load all fragments for one kk (k16 step) into buffer slot
__device__ __forceinline__ void load_frags(uint32_t st, int kk, int m_w, int n_w, int lane,
                                           uint32_t (*ah)[4], uint32_t (*al)[4], uint32_t (*bh)[2]) {
    int cbase = kk * 2;
    #pragma unroll
    for (int mi = 0; mi < 2; mi++) {
        int r = m_w + mi * 16 + (lane & 15);
        uint32_t ch = (uint32_t)((cbase + (lane >> 4)) ^ (r & 7));
        uint32_t off = (uint32_t)r * 128 + ch * 16;
        ldm_x4(ah[mi][0], ah[mi][1], ah[mi][2], ah[mi][3], st + off);
        ldm_x4(al[mi][0], al[mi][1], al[mi][2], al[mi][3], st + ABUF + off);
    }
    #pragma unroll
    for (int nip = 0; nip < 2; nip++) {
        int g = lane >> 3;
        int r = n_w + (nip * 2 + (g >> 1)) * 8 + (lane & 7);
        uint32_t ch = (uint32_t)((cbase + (g & 1)) ^ (r & 7));
        uint32_t off = (uint32_t)r * 128 + ch * 16;
        ldm_x4(bh[nip*2][0], bh[nip*2][1], bh[nip*2+1][0], bh[nip*2+1][1],
               st + 2 * ABUF + off);
    }
}

// G2=false: GEMM1  x@W1^T + relu/bias/p epilogue -> hs fp16 hi/lo
// G2=true : GEMM2  hs@W2cat^T (split-K over 8) -> fp32 partials
template<bool G2>
__global__ void __launch_bounds__(256, 2) k_gemm_tc(const float* __restrict__ b1) {
    extern __shared__ char smem[];
    uint32_t sbase = smem_to_u32(smem);
    int tid = threadIdx.x;
    int wid = tid >> 5, lane = tid & 31;
    int m_w = (wid & 3) * 32;           // 4 warps over M
    int n_w = (wid >> 2) * 32;          // 2 warps over N
    int m0 = blockIdx.y * TILE_M;

    constexpr int LD    = G2 ? HC : D_;
    constexpr int niter = G2 ? NITER2 : NITER1;
    const __half* Ah = G2 ? g_hsh : g_xh;
    const __half* Al = G2 ? g_hsl : g_xl;
    const __half* Bh = G2 ? g_w2h : g_wh;
    int n0    = G2 ? (blockIdx.x & 1) * TILE_N : blockIdx.x * TILE_N;
    int kbase = G2 ? (blockIdx.x >> 1) * KCH2 : 0;

    float acc[2][4][4] = {};
    uint32_t fah[2][2][4], fal[2][2][4], fbh[2][4][2];

    stage_prefetch<LD>(sbase, 0, Ah, Al, Bh, m0, n0, kbase, tid);
    cp_commit();
    stage_prefetch<LD>(sbase, 1, Ah, Al, Bh, m0, n0, kbase + KCHUNK, tid);
    cp_commit();

    for (int i = 0; i < niter; i++) {
        int s = i & 1;
        cp_wait<1>();
        __syncthreads();

        uint32_t st = sbase + s * STAGE_BYTES;
        // prime fragment pipeline
        load_frags(st, 0, m_w, n_w, lane, fah[0], fal[0], fbh[0]);
        #pragma unroll
        for (int kk = 0; kk < 4; kk++) {
            int cur = kk & 1, nxt = cur ^ 1;
            if (kk < 3)
                load_frags(st, kk + 1, m_w, n_w, lane, fah[nxt], fal[nxt], fbh[nxt]);
            #pragma unroll
            for (int mi = 0; mi < 2; mi++)
                #pragma unroll
                for (int ni = 0; ni < 4; ni++) {
                    mma_fp16(acc[mi][ni], fah[cur][mi], fbh[cur][ni]);
                    mma_fp16(acc[mi][ni], fal[cur][mi], fbh[cur][ni]);
                }
        }
        __syncthreads();
        if (i + NSTAGE < niter)
            stage_prefetch<LD>(sbase, s, Ah, Al, Bh, m0, n0, kbase + (i + NSTAGE) * KCHUNK, tid);
        cp_commit();
    }

    int trow = lane >> 2;
    int tcol = (lane & 3) * 2;
    if (!G2) {
        int leaf = n0 >> 8;
        #pragma unroll
        for (int mi = 0; mi < 2; mi++) {
            int mA = m0 + m_w + mi * 16 + trow;
            int mB = mA + 8;
            float pA = g_p[leaf * B_ + mA];
            float pB = g_p[leaf * B_ + mB];
            #pragma unroll
            for (int ni = 0; ni < 4; ni++) {
                int n = n0 + n_w + ni * 8 + tcol;
                float bv0 = __ldg(&b1[n]), bv1 = __ldg(&b1[n + 1]);
                float v00 = fmaxf(acc[mi][ni][0] + bv0, 0.f) * pA;
                float v01 = fmaxf(acc[mi][ni][1] + bv1, 0.f) * pA;
                float v10 = fmaxf(acc[mi][ni][2] + bv0, 0.f) * pB;
                float v11 = fmaxf(acc[mi][ni][3] + bv1, 0.f) * pB;
                __half h00 = __float2half_rn(v00), h01 = __float2half_rn(v01);
                __half h10 = __float2half_rn(v10), h11 = __float2half_rn(v11);
                __half l00 = __float2half_rn(v00 - __half2float(h00));
                __half l01 = __float2half_rn(v01 - __half2float(h01));
                __half l10 = __float2half_rn(v10 - __half2float(h10));
                __half l11 = __float2half_rn(v11 - __half2float(h11));
                size_t iA = (size_t)mA * HC + n, iB = (size_t)mB * HC + n;
                *(__half2*)&g_hsh[iA] = __half2(h00, h01);
                *(__half2*)&g_hsl[iA] = __half2(l00, l01);
                *(__half2*)&g_hsh[iB] = __half2(h10, h11);
                *(__half2*)&g_hsl[iB] = __half2(l10, l11);
            }
        }
    } else {
        float* part = g_part[blockIdx.x >> 1];
        #pragma unroll
        for (int mi = 0; mi < 2; mi++) {
            int mA = m0 + m_w + mi * 16 + trow;
            int mB = mA + 8;
            #pragma unroll
            for (int ni = 0; ni < 4; ni++) {
                int n = n0 + n_w + ni * 8 + tcol;
                *(float2*)&part[(size_t)mA * 128 + n] = make_float2(acc[mi][ni][0], acc[mi][ni][1]);
                *(float2*)&part[(size_t)mB * 128 + n] = make_float2(acc[mi][ni][2], acc[mi][ni][3]);
            }
        }
    }
}

// ============================================================
// Kernel 6: reduce split-K + leaf-weighted b2
// ============================================================
__global__ void k_reduce(const float* __restrict__ b2, float* __restrict__ out) {
    int idx = blockIdx.x * blockDim.x + threadIdx.x;
    if (idx >= B_ * NC) return;
    int b = idx / NC;
    int c = idx - b * NC;
    float v = 0.f;
    #pragma unroll
    for (int s = 0; s < KSPLIT2; s++) v += g_part[s][(size_t)b * 128 + c];
    float bias = 0.f;
    #pragma unroll
    for (int l = 0; l < NL; l++) bias += g_p[l * B_ + b] * b2[l * NC + c];
    out[idx] = v + bias;
}

extern "C" void kernel_launch(void* const* d_in, const int* in_sizes, int n_in,
                              void* d_out, int out_size) {
    const float* x   = (const float*)d_in[0];
    const float* u   = (const float*)d_in[1];
    const float* fl  = (const float*)d_in[2];
    const float* thr = (const float*)d_in[3];
    const float* fw  = (const float*)d_in[4];
    const float* W1  = (const float*)d_in[5];
    const float* b1  = (const float*)d_in[6];
    const float* W2  = (const float*)d_in[7];
    const float* b2  = (const float*)d_in[8];
    float* out = (float*)d_out;

    cudaFuncSetAttribute(k_gemm_tc<false>, cudaFuncAttributeMaxDynamicSharedMemorySize, SMEM_TOTAL);
    cudaFuncSetAttribute(k_gemm_tc<true>,  cudaFuncAttributeMaxDynamicSharedMemorySize, SMEM_TOTAL);

    // launch order: k_gemm_tc<false> stays launch #3 (profiled slot)
    k_split_all<<<(N4X + N4W + 255) / 256, 256>>>(x, W1);
    k_gumbel_split<<<NI * B_ / 8, 256>>>(x, u, fl, thr, fw);
    k_leaf_probs<<<B_ / 256, 256>>>();
    k_gemm_tc<false><<<dim3(HC / TILE_N, B_ / TILE_M), 256, SMEM_TOTAL>>>(b1);
    k_pack_w2<<<(128 * HC + 255) / 256, 256>>>(W2);
    k_gemm_tc<true><<<dim3(KSPLIT2 * 2, B_ / TILE_M), 256, SMEM_TOTAL>>>(nullptr);
    k_reduce<<<(B_ * NC + 255) / 256, 256>>>(b2, out);
}

// round 8
// speedup vs baseline: 5.1805x; 1.6664x over previous
#include <cuda_runtime.h>
#include <cuda_fp16.h>
#include <cstdint>

#define B_    4096
#define D_    1024
#define NI    15
#define NL    16
#define NH    256
#define NC    100
#define HC    4096
#define EPSF  1e-10f

// GEMM tiling: 128(M) x 128(N) x 64(K-stage), 3 stages, 2 CTAs/SM
#define TILE_M 128
#define TILE_N 128
#define KCHUNK 64
#define NITER1 (D_ / KCHUNK)            // 16 (GEMM1)
#define KSPLIT2 8
#define KCH2   (HC / KSPLIT2)           // 512
#define NITER2 (KCH2 / KCHUNK)          // 8 (GEMM2)
#define ABUF   (TILE_M * 128)           // 16KB
#define BBUF   (TILE_N * 128)           // 16KB
#define STAGE_BYTES (ABUF + BBUF)       // 32KB
#define NSTAGE 3
#define SMEM_TOTAL (NSTAGE * STAGE_BYTES) // 96KB -> 2 CTAs/SM

// ---- scratch (device globals) ----
__device__ float g_split[NI * B_];
__device__ float g_p[NL * B_];
__device__ float g_part[KSPLIT2][(size_t)B_ * 128];
__device__ __half g_xh[(size_t)B_ * D_];
__device__ __half g_wh[(size_t)HC * D_];
__device__ __half g_hs[(size_t)B_ * HC];
__device__ __half g_w2h[(size_t)128 * HC];

// ============================================================
// helpers
// ============================================================
__device__ __forceinline__ uint32_t smem_to_u32(const void* p) {
    uint32_t a;
    asm("{ .reg .u64 t; cvta.to.shared.u64 t, %1; cvt.u32.u64 %0, t; }" : "=r"(a) : "l"(p));
    return a;
}
__device__ __forceinline__ void cp_async16(uint32_t dst, const void* src) {
    asm volatile("cp.async.cg.shared.global [%0], [%1], 16;" :: "r"(dst), "l"(src));
}
__device__ __forceinline__ void cp_commit() { asm volatile("cp.async.commit_group;"); }
template<int N> __device__ __forceinline__ void cp_wait() {
    asm volatile("cp.async.wait_group %0;" :: "n"(N));
}
__device__ __forceinline__ void ldm_x4(uint32_t& r0, uint32_t& r1, uint32_t& r2, uint32_t& r3, uint32_t addr) {
    asm volatile("ldmatrix.sync.aligned.m8n8.x4.shared.b16 {%0,%1,%2,%3}, [%4];"
                 : "=r"(r0), "=r"(r1), "=r"(r2), "=r"(r3) : "r"(addr));
}
__device__ __forceinline__ void mma_fp16(float* d, const uint32_t* a, const uint32_t* b) {
    asm volatile("mma.sync.aligned.m16n8k16.row.col.f32.f16.f16.f32 "
                 "{%0,%1,%2,%3}, {%4,%5,%6,%7}, {%8,%9}, {%0,%1,%2,%3};"
                 : "+f"(d[0]), "+f"(d[1]), "+f"(d[2]), "+f"(d[3])
                 : "r"(a[0]), "r"(a[1]), "r"(a[2]), "r"(a[3]), "r"(b[0]), "r"(b[1]));
}

// ============================================================
// Kernel 0: fp32 -> fp16 conversion for x and W1
// ============================================================
#define N4X (B_ * D_ / 4)
#define N4W (HC * D_ / 4)
__global__ void k_tofp16(const float* __restrict__ x, const float* __restrict__ w) {
    int i = blockIdx.x * blockDim.x + threadIdx.x;
    const float* s;
    __half* dst;
    int j;
    if (i < N4X) { s = x; dst = g_xh; j = i; }
    else if (i < N4X + N4W) { s = w; dst = g_wh; j = i - N4X; }
    else return;
    float4 v = ((const float4*)s)[j];
    ((__half2*)dst)[2*j]   = __half2(__float2half_rn(v.x), __float2half_rn(v.y));
    ((__half2*)dst)[2*j+1] = __half2(__float2half_rn(v.z), __float2half_rn(v.w));
}

// ============================================================
// Kernel 1: gumbel gate + split sigmoid (warp per row)
// ============================================================
__global__ void k_gumbel_split(const float* __restrict__ x,
                               const float* __restrict__ u,
                               const float* __restrict__ fl,
                               const float* __restrict__ thr,
                               const float* __restrict__ fw) {
    int row  = blockIdx.x * 8 + (threadIdx.x >> 5);
    int lane = threadIdx.x & 31;
    int n = row / B_;
    int b = row - n * B_;
    const float4* u4  = (const float4*)(u  + (size_t)row * D_);
    const float4* x4  = (const float4*)(x  + (size_t)b   * D_);
    const float4* fl4 = (const float4*)(fl + n * D_);
    const float4* fw4 = (const float4*)(fw + n * D_);

    float s0 = 0.f, s1 = 0.f;
    #pragma unroll
    for (int i = 0; i < 8; i++) {
        int idx = i * 32 + lane;
        float4 uv = u4[idx], xv = x4[idx], flv = fl4[idx], fwv = fw4[idx];
        float e;
        e = __expf(flv.x - __logf(-__logf(uv.x + EPSF) + EPSF)); s0 += e; s1 += e * xv.x * fwv.x;
        e = __expf(flv.y - __logf(-__logf(uv.y + EPSF) + EPSF)); s0 += e; s1 += e * xv.y * fwv.y;
        e = __expf(flv.z - __logf(-__logf(uv.z + EPSF) + EPSF)); s0 += e; s1 += e * xv.z * fwv.z;
        e = __expf(flv.w - __logf(-__logf(uv.w + EPSF) + EPSF)); s0 += e; s1 += e * xv.w * fwv.w;
    }
    #pragma unroll
    for (int off = 16; off; off >>= 1) {
        s0 += __shfl_down_sync(0xffffffffu, s0, off);
        s1 += __shfl_down_sync(0xffffffffu, s1, off);
    }
    if (lane == 0) {
        float z = s1 / s0 - thr[n];
        g_split[row] = 1.f / (1.f + __expf(-z));
    }
}

// ============================================================
// Kernel 2: leaf routing probabilities
// ============================================================
__global__ void k_leaf_probs() {
    int b = blockIdx.x * blockDim.x + threadIdx.x;
    if (b >= B_) return;
    float s[NI];
    #pragma unroll
    for (int i = 0; i < NI; i++) s[i] = g_split[i * B_ + b];
    #pragma unroll
    for (int l = 0; l < NL; l++) {
        float p = 1.f;
        int pos = 0;
        #pragma unroll
        for (int k = 0; k < 4; k++) {
            int bit = (l >> (3 - k)) & 1;
            float sv = s[(1 << k) - 1 + pos];
            p *= bit ? sv : (1.f - sv);
            pos = 2 * pos + bit;
        }
        g_p[l * B_ + b] = p;
    }
}

// ============================================================
// Kernel 3: pack W2 [16][100][256] -> fp16 [128 pad][4096]
// ============================================================
__global__ void k_pack_w2(const float* __restrict__ W2) {
    int idx = blockIdx.x * blockDim.x + threadIdx.x;
    if (idx >= 128 * HC) return;
    int c = idx / HC;
    int j = idx - c * HC;
    int l = j >> 8;
    int h = j & 255;
    float v = (c < NC) ? W2[((size_t)l * NC + c) * NH + h] : 0.f;
    g_w2h[idx] = __float2half_rn(v);
}

// ============================================================
// shared HMMA mainloop (128x128 tile, fp16 single-term)
// ============================================================
template<int LD>
__device__ __forceinline__ void stage_prefetch(uint32_t sbase, int stage,
                                               const __half* A, const __half* Bm,
                                               int m0, int n0, int k0, int tid) {
    uint32_t st = sbase + stage * STAGE_BYTES;
    int r  = tid >> 1;              // 0..127
    int cs = (tid & 1) * 4;         // 0 or 4
    const __half* sa = A  + (size_t)(m0 + r) * LD + k0;
    const __half* sb = Bm + (size_t)(n0 + r) * LD + k0;
    uint32_t rb_a = st + r * 128;
    uint32_t rb_b = st + ABUF + r * 128;
    #pragma unroll
    for (int c = cs; c < cs + 4; c++) {
        uint32_t phys = (uint32_t)(c ^ (r & 7)) * 16;
        cp_async16(rb_a + phys, sa + c * 8);
        cp_async16(rb_b + phys, sb + c * 8);
    }
}

// G2=false: GEMM1  x@W1^T + relu/bias/p epilogue -> hs fp16
// G2=true : GEMM2  hs@W2cat^T (split-K over 8) -> fp32 partials
template<bool G2>
__global__ void __launch_bounds__(256, 2) k_gemm_tc(const float* __restrict__ b1) {
    extern __shared__ char smem[];
    uint32_t sbase = smem_to_u32(smem);
    int tid = threadIdx.x;
    int wid = tid >> 5, lane = tid & 31;
    int m_w = (wid & 1) * 64;           // 2 warps over M (64 rows each)
    int n_w = (wid >> 1) * 32;          // 4 warps over N (32 cols each)
    int m0 = blockIdx.y * TILE_M;

    constexpr int LD    = G2 ? HC : D_;
    constexpr int niter = G2 ? NITER2 : NITER1;
    const __half* A  = G2 ? g_hs  : g_xh;
    const __half* Bm = G2 ? g_w2h : g_wh;
    int n0    = G2 ? 0 : blockIdx.x * TILE_N;
    int kbase = G2 ? blockIdx.x * KCH2 : 0;

    float acc[4][4][4] = {};

    stage_prefetch<LD>(sbase, 0, A, Bm, m0, n0, kbase, tid);
    cp_commit();
    stage_prefetch<LD>(sbase, 1, A, Bm, m0, n0, kbase + KCHUNK, tid);
    cp_commit();
    stage_prefetch<LD>(sbase, 2, A, Bm, m0, n0, kbase + 2 * KCHUNK, tid);
    cp_commit();

    for (int i = 0; i < niter; i++) {
        int s = i % NSTAGE;
        cp_wait<2>();
        __syncthreads();

        uint32_t st = sbase + s * STAGE_BYTES;
        #pragma unroll
        for (int kk = 0; kk < 4; kk++) {
            int cbase = kk * 2;
            uint32_t ah[4][4], bh[4][2];
            #pragma unroll
            for (int mi = 0; mi < 4; mi++) {
                int r = m_w + mi * 16 + (lane & 15);
                uint32_t ch = (uint32_t)((cbase + (lane >> 4)) ^ (r & 7));
                uint32_t off = (uint32_t)r * 128 + ch * 16;
                ldm_x4(ah[mi][0], ah[mi][1], ah[mi][2], ah[mi][3], st + off);
            }
            // B: one x4 covers (ni, ni+1) x (k-chunk 0,1)
            #pragma unroll
            for (int nip = 0; nip < 2; nip++) {
                int g = lane >> 3;
                int r = n_w + (nip * 2 + (g >> 1)) * 8 + (lane & 7);
                uint32_t ch = (uint32_t)((cbase + (g & 1)) ^ (r & 7));
                uint32_t off = (uint32_t)r * 128 + ch * 16;
                ldm_x4(bh[nip*2][0], bh[nip*2][1], bh[nip*2+1][0], bh[nip*2+1][1],
                       st + ABUF + off);
            }
            #pragma unroll
            for (int mi = 0; mi < 4; mi++)
                #pragma unroll
                for (int ni = 0; ni < 4; ni++)
                    mma_fp16(acc[mi][ni], ah[mi], bh[ni]);
        }
        __syncthreads();
        if (i + NSTAGE < niter)
            stage_prefetch<LD>(sbase, s, A, Bm, m0, n0, kbase + (i + NSTAGE) * KCHUNK, tid);
        cp_commit();
    }

    int trow = lane >> 2;
    int tcol = (lane & 3) * 2;
    if (!G2) {
        int leaf = n0 >> 8;
        #pragma unroll
        for (int mi = 0; mi < 4; mi++) {
            int mA = m0 + m_w + mi * 16 + trow;
            int mB = mA + 8;
            float pA = g_p[leaf * B_ + mA];
            float pB = g_p[leaf * B_ + mB];
            #pragma unroll
            for (int ni = 0; ni < 4; ni++) {
                int n = n0 + n_w + ni * 8 + tcol;
                float bv0 = __ldg(&b1[n]), bv1 = __ldg(&b1[n + 1]);
                float v00 = fmaxf(acc[mi][ni][0] + bv0, 0.f) * pA;
                float v01 = fmaxf(acc[mi][ni][1] + bv1, 0.f) * pA;
                float v10 = fmaxf(acc[mi][ni][2] + bv0, 0.f) * pB;
                float v11 = fmaxf(acc[mi][ni][3] + bv1, 0.f) * pB;
                *(__half2*)&g_hs[(size_t)mA * HC + n] =
                    __half2(__float2half_rn(v00), __float2half_rn(v01));
                *(__half2*)&g_hs[(size_t)mB * HC + n] =
                    __half2(__float2half_rn(v10), __float2half_rn(v11));
            }
        }
    } else {
        float* part = g_part[blockIdx.x];
        #pragma unroll
        for (int mi = 0; mi < 4; mi++) {
            int mA = m0 + m_w + mi * 16 + trow;
            int mB = mA + 8;
            #pragma unroll
            for (int ni = 0; ni < 4; ni++) {
                int n = n_w + ni * 8 + tcol;
                *(float2*)&part[(size_t)mA * 128 + n] = make_float2(acc[mi][ni][0], acc[mi][ni][1]);
                *(float2*)&part[(size_t)mB * 128 + n] = make_float2(acc[mi][ni][2], acc[mi][ni][3]);
            }
        }
    }
}

// ============================================================
// Kernel 6: reduce split-K + leaf-weighted b2
// ============================================================
__global__ void k_reduce(const float* __restrict__ b2, float* __restrict__ out) {
    int idx = blockIdx.x * blockDim.x + threadIdx.x;
    if (idx >= B_ * NC) return;
    int b = idx / NC;
    int c = idx - b * NC;
    float v = 0.f;
    #pragma unroll
    for (int s = 0; s < KSPLIT2; s++) v += g_part[s][(size_t)b * 128 + c];
    float bias = 0.f;
    #pragma unroll
    for (int l = 0; l < NL; l++) bias += g_p[l * B_ + b] * b2[l * NC + c];
    out[idx] = v + bias;
}

extern "C" void kernel_launch(void* const* d_in, const int* in_sizes, int n_in,
                              void* d_out, int out_size) {
    const float* x   = (const float*)d_in[0];
    const float* u   = (const float*)d_in[1];
    const float* fl  = (const float*)d_in[2];
    const float* thr = (const float*)d_in[3];
    const float* fw  = (const float*)d_in[4];
    const float* W1  = (const float*)d_in[5];
    const float* b1  = (const float*)d_in[6];
    const float* W2  = (const float*)d_in[7];
    const float* b2  = (const float*)d_in[8];
    float* out = (float*)d_out;

    cudaFuncSetAttribute(k_gemm_tc<false>, cudaFuncAttributeMaxDynamicSharedMemorySize, SMEM_TOTAL);
    cudaFuncSetAttribute(k_gemm_tc<true>,  cudaFuncAttributeMaxDynamicSharedMemorySize, SMEM_TOTAL);

    // launch order: k_gemm_tc<false> stays launch #3 (profiled slot)
    k_tofp16<<<(N4X + N4W + 255) / 256, 256>>>(x, W1);
    k_gumbel_split<<<NI * B_ / 8, 256>>>(x, u, fl, thr, fw);
    k_leaf_probs<<<B_ / 256, 256>>>();
    k_gemm_tc<false><<<dim3(HC / TILE_N, B_ / TILE_M), 256, SMEM_TOTAL>>>(b1);
    k_pack_w2<<<(128 * HC + 255) / 256, 256>>>(W2);
    k_gemm_tc<true><<<dim3(KSPLIT2, B_ / TILE_M), 256, SMEM_TOTAL>>>(nullptr);
    k_reduce<<<(B_ * NC + 255) / 256, 256>>>(b2, out);
}

// round 9
// speedup vs baseline: 5.1887x; 1.0016x over previous
#include <cuda_runtime.h>
#include <cuda_fp16.h>
#include <cstdint>

#define B_    4096
#define D_    1024
#define NI    15
#define NL    16
#define NH    256
#define NC    100
#define HC    4096
#define EPSF  1e-10f

// GEMM tiling: 128(M) x 128(N) x 64(K-stage), 3 stages, 2 CTAs/SM
#define TILE_M 128
#define TILE_N 128
#define KCHUNK 64
#define NITER1 (D_ / KCHUNK)            // 16 (GEMM1)
#define KSPLIT2 8
#define KCH2   (HC / KSPLIT2)           // 512
#define NITER2 (KCH2 / KCHUNK)          // 8 (GEMM2)
#define ABUF   (TILE_M * 128)           // 16KB
#define BBUF   (TILE_N * 128)           // 16KB
#define STAGE_BYTES (ABUF + BBUF)       // 32KB
#define NSTAGE 3
#define SMEM_TOTAL (NSTAGE * STAGE_BYTES) // 96KB -> 2 CTAs/SM

// ---- scratch (device globals) ----
__device__ float g_split[NI * B_];
__device__ float g_p[NL * B_];
__device__ float g_part[KSPLIT2][(size_t)B_ * 128];
__device__ float g_efl[NI * D_];        // exp(feature_logits)
__device__ float g_c1[NI * D_];         // exp(fl) * fw
__device__ __half g_xh[(size_t)B_ * D_];
__device__ __half g_wh[(size_t)HC * D_];
__device__ __half g_hs[(size_t)B_ * HC];
__device__ __half g_w2h[(size_t)128 * HC];

// ============================================================
// helpers
// ============================================================
__device__ __forceinline__ uint32_t smem_to_u32(const void* p) {
    uint32_t a;
    asm("{ .reg .u64 t; cvta.to.shared.u64 t, %1; cvt.u32.u64 %0, t; }" : "=r"(a) : "l"(p));
    return a;
}
__device__ __forceinline__ void cp_async16(uint32_t dst, const void* src) {
    asm volatile("cp.async.cg.shared.global [%0], [%1], 16;" :: "r"(dst), "l"(src));
}
__device__ __forceinline__ void cp_commit() { asm volatile("cp.async.commit_group;"); }
template<int N> __device__ __forceinline__ void cp_wait() {
    asm volatile("cp.async.wait_group %0;" :: "n"(N));
}
__device__ __forceinline__ void ldm_x4(uint32_t& r0, uint32_t& r1, uint32_t& r2, uint32_t& r3, uint32_t addr) {
    asm volatile("ldmatrix.sync.aligned.m8n8.x4.shared.b16 {%0,%1,%2,%3}, [%4];"
                 : "=r"(r0), "=r"(r1), "=r"(r2), "=r"(r3) : "r"(addr));
}
__device__ __forceinline__ void mma_fp16(float* d, const uint32_t* a, const uint32_t* b) {
    asm volatile("mma.sync.aligned.m16n8k16.row.col.f32.f16.f16.f32 "
                 "{%0,%1,%2,%3}, {%4,%5,%6,%7}, {%8,%9}, {%0,%1,%2,%3};"
                 : "+f"(d[0]), "+f"(d[1]), "+f"(d[2]), "+f"(d[3])
                 : "r"(a[0]), "r"(a[1]), "r"(a[2]), "r"(a[3]), "r"(b[0]), "r"(b[1]));
}
__device__ __forceinline__ float frcp(float x) {
    float r;
    asm("rcp.approx.f32 %0, %1;" : "=f"(r) : "f"(x));
    return r;
}

// ============================================================
// Kernel 0 (prep): x->fp16, W1->fp16, W2 pack->fp16, exp(fl)/c1 tables
// ============================================================
#define N4X (B_ * D_ / 4)               // 1048576
#define N4W (HC * D_ / 4)               // 1048576
#define N4P (128 * HC / 4)              // 131072
#define N4F (NI * D_ / 4)               // 3840
__global__ void k_prep(const float* __restrict__ x, const float* __restrict__ w,
                       const float* __restrict__ W2,
                       const float* __restrict__ fl, const float* __restrict__ fw) {
    int i = blockIdx.x * blockDim.x + threadIdx.x;
    if (i < N4X) {
        float4 v = ((const float4*)x)[i];
        ((__half2*)g_xh)[2*i]   = __half2(__float2half_rn(v.x), __float2half_rn(v.y));
        ((__half2*)g_xh)[2*i+1] = __half2(__float2half_rn(v.z), __float2half_rn(v.w));
    } else if (i < N4X + N4W) {
        int j = i - N4X;
        float4 v = ((const float4*)w)[j];
        ((__half2*)g_wh)[2*j]   = __half2(__float2half_rn(v.x), __float2half_rn(v.y));
        ((__half2*)g_wh)[2*j+1] = __half2(__float2half_rn(v.z), __float2half_rn(v.w));
    } else if (i < N4X + N4W + N4P) {
        int j4 = i - N4X - N4W;         // 0..131071
        int c  = j4 >> 10;              // 128 rows, 1024 float4 per row
        int jj = (j4 & 1023) * 4;       // col in [0,4096)
        int l  = jj >> 8;
        int h  = jj & 255;
        float4 v = (c < NC) ? *(const float4*)&W2[((size_t)l * NC + c) * NH + h]
                            : make_float4(0.f, 0.f, 0.f, 0.f);
        ((__half2*)g_w2h)[(size_t)(c * HC + jj) / 2]     = __half2(__float2half_rn(v.x), __float2half_rn(v.y));
        ((__half2*)g_w2h)[(size_t)(c * HC + jj) / 2 + 1] = __half2(__float2half_rn(v.z), __float2half_rn(v.w));
    } else if (i < N4X + N4W + N4P + N4F) {
        int q = i - N4X - N4W - N4P;
        float4 f = ((const float4*)fl)[q];
        float4 w4 = ((const float4*)fw)[q];
        float4 e, c;
        e.x = __expf(f.x); e.y = __expf(f.y); e.z = __expf(f.z); e.w = __expf(f.w);
        c.x = e.x * w4.x;  c.y = e.y * w4.y;  c.z = e.z * w4.z;  c.w = e.w * w4.w;
        ((float4*)g_efl)[q] = e;
        ((float4*)g_c1)[q]  = c;
    }
}

// ============================================================
// Kernel 1: gumbel gate + split sigmoid (warp per row)
// e = exp(fl+g) = exp(fl) / (-log(u+eps) + eps)   [exact algebra]
// ============================================================
__global__ void k_gumbel_split(const float* __restrict__ x,
                               const float* __restrict__ u,
                               const float* __restrict__ thr) {
    int row  = blockIdx.x * 8 + (threadIdx.x >> 5);
    int lane = threadIdx.x & 31;
    int n = row / B_;
    int b = row - n * B_;
    const float4* u4 = (const float4*)(u + (size_t)row * D_);
    const float4* x4 = (const float4*)(x + (size_t)b   * D_);
    const float4* e4 = (const float4*)(g_efl + n * D_);
    const float4* c4 = (const float4*)(g_c1  + n * D_);

    float s0 = 0.f, s1 = 0.f;
    #pragma unroll
    for (int i = 0; i < 8; i++) {
        int idx = i * 32 + lane;
        float4 uv = u4[idx], xv = x4[idx], ev = e4[idx], cv = c4[idx];
        float r;
        r = frcp(-__logf(uv.x + EPSF) + EPSF); s0 = fmaf(ev.x, r, s0); s1 = fmaf(cv.x * xv.x, r, s1);
        r = frcp(-__logf(uv.y + EPSF) + EPSF); s0 = fmaf(ev.y, r, s0); s1 = fmaf(cv.y * xv.y, r, s1);
        r = frcp(-__logf(uv.z + EPSF) + EPSF); s0 = fmaf(ev.z, r, s0); s1 = fmaf(cv.z * xv.z, r, s1);
        r = frcp(-__logf(uv.w + EPSF) + EPSF); s0 = fmaf(ev.w, r, s0); s1 = fmaf(cv.w * xv.w, r, s1);
    }
    #pragma unroll
    for (int off = 16; off; off >>= 1) {
        s0 += __shfl_down_sync(0xffffffffu, s0, off);
        s1 += __shfl_down_sync(0xffffffffu, s1, off);
    }
    if (lane == 0) {
        float z = s1 / s0 - thr[n];
        g_split[row] = 1.f / (1.f + __expf(-z));
    }
}

// ============================================================
// Kernel 2: leaf routing probabilities
// ============================================================
__global__ void k_leaf_probs() {
    int b = blockIdx.x * blockDim.x + threadIdx.x;
    if (b >= B_) return;
    float s[NI];
    #pragma unroll
    for (int i = 0; i < NI; i++) s[i] = g_split[i * B_ + b];
    #pragma unroll
    for (int l = 0; l < NL; l++) {
        float p = 1.f;
        int pos = 0;
        #pragma unroll
        for (int k = 0; k < 4; k++) {
            int bit = (l >> (3 - k)) & 1;
            float sv = s[(1 << k) - 1 + pos];
            p *= bit ? sv : (1.f - sv);
            pos = 2 * pos + bit;
        }
        g_p[l * B_ + b] = p;
    }
}

// ============================================================
// shared HMMA mainloop (128x128 tile, fp16, frag double-buffered)
// ============================================================
template<int LD>
__device__ __forceinline__ void stage_prefetch(uint32_t sbase, int stage,
                                               const __half* A, const __half* Bm,
                                               int m0, int n0, int k0, int tid) {
    uint32_t st = sbase + stage * STAGE_BYTES;
    int r  = tid >> 1;
    int cs = (tid & 1) * 4;
    const __half* sa = A  + (size_t)(m0 + r) * LD + k0;
    const __half* sb = Bm + (size_t)(n0 + r) * LD + k0;
    uint32_t rb_a = st + r * 128;
    uint32_t rb_b = st + ABUF + r * 128;
    #pragma unroll
    for (int c = cs; c < cs + 4; c++) {
        uint32_t phys = (uint32_t)(c ^ (r & 7)) * 16;
        cp_async16(rb_a + phys, sa + c * 8);
        cp_async16(rb_b + phys, sb + c * 8);
    }
}

__device__ __forceinline__ void load_a(uint32_t st, int kk, int m_w, int lane, uint32_t (*ah)[4]) {
    int cbase = kk * 2;
    #pragma unroll
    for (int mi = 0; mi < 4; mi++) {
        int r = m_w + mi * 16 + (lane & 15);
        uint32_t ch = (uint32_t)((cbase + (lane >> 4)) ^ (r & 7));
        uint32_t off = (uint32_t)r * 128 + ch * 16;
        ldm_x4(ah[mi][0], ah[mi][1], ah[mi][2], ah[mi][3], st + off);
    }
}
__device__ __forceinline__ void load_b(uint32_t st, int kk, int n_w, int lane, uint32_t (*bh)[2]) {
    int cbase = kk * 2;
    #pragma unroll
    for (int nip = 0; nip < 2; nip++) {
        int g = lane >> 3;
        int r = n_w + (nip * 2 + (g >> 1)) * 8 + (lane & 7);
        uint32_t ch = (uint32_t)((cbase + (g & 1)) ^ (r & 7));
        uint32_t off = (uint32_t)r * 128 + ch * 16;
        ldm_x4(bh[nip*2][0], bh[nip*2][1], bh[nip*2+1][0], bh[nip*2+1][1],
               st + ABUF + off);
    }
}

// G2=false: GEMM1  x@W1^T + relu/bias/p epilogue -> hs fp16
// G2=true : GEMM2  hs@W2cat^T (split-K over 8) -> fp32 partials
template<bool G2>
__global__ void __launch_bounds__(256, 2) k_gemm_tc(const float* __restrict__ b1) {
    extern __shared__ char smem[];
    uint32_t sbase = smem_to_u32(smem);
    int tid = threadIdx.x;
    int wid = tid >> 5, lane = tid & 31;
    int m_w = (wid & 1) * 64;           // 2 warps over M
    int n_w = (wid >> 1) * 32;          // 4 warps over N
    int m0 = blockIdx.y * TILE_M;

    constexpr int LD    = G2 ? HC : D_;
    constexpr int niter = G2 ? NITER2 : NITER1;
    const __half* A  = G2 ? g_hs  : g_xh;
    const __half* Bm = G2 ? g_w2h : g_wh;
    int n0    = G2 ? 0 : blockIdx.x * TILE_N;
    int kbase = G2 ? blockIdx.x * KCH2 : 0;

    float acc[4][4][4] = {};
    uint32_t ah[2][4][4], bh[2][4][2];

    stage_prefetch<LD>(sbase, 0, A, Bm, m0, n0, kbase, tid);
    cp_commit();
    stage_prefetch<LD>(sbase, 1, A, Bm, m0, n0, kbase + KCHUNK, tid);
    cp_commit();
    stage_prefetch<LD>(sbase, 2, A, Bm, m0, n0, kbase + 2 * KCHUNK, tid);
    cp_commit();

    for (int i = 0; i < niter; i++) {
        int s = i % NSTAGE;
        cp_wait<2>();
        __syncthreads();

        uint32_t st = sbase + s * STAGE_BYTES;
        load_a(st, 0, m_w, lane, ah[0]);
        load_b(st, 0, n_w, lane, bh[0]);
        #pragma unroll
        for (int kk = 0; kk < 4; kk++) {
            int cur = kk & 1, nxt = cur ^ 1;
            if (kk < 3) {
                load_a(st, kk + 1, m_w, lane, ah[nxt]);
                load_b(st, kk + 1, n_w, lane, bh[nxt]);
            }
            #pragma unroll
            for (int mi = 0; mi < 4; mi++)
                #pragma unroll
                for (int ni = 0; ni < 4; ni++)
                    mma_fp16(acc[mi][ni], ah[cur][mi], bh[cur][ni]);
        }
        __syncthreads();
        if (i + NSTAGE < niter)
            stage_prefetch<LD>(sbase, s, A, Bm, m0, n0, kbase + (i + NSTAGE) * KCHUNK, tid);
        cp_commit();
    }

    int trow = lane >> 2;
    int tcol = (lane & 3) * 2;
    if (!G2) {
        int leaf = n0 >> 8;
        #pragma unroll
        for (int mi = 0; mi < 4; mi++) {
            int mA = m0 + m_w + mi * 16 + trow;
            int mB = mA + 8;
            float pA = g_p[leaf * B_ + mA];
            float pB = g_p[leaf * B_ + mB];
            #pragma unroll
            for (int ni = 0; ni < 4; ni++) {
                int n = n0 + n_w + ni * 8 + tcol;
                float bv0 = __ldg(&b1[n]), bv1 = __ldg(&b1[n + 1]);
                float v00 = fmaxf(acc[mi][ni][0] + bv0, 0.f) * pA;
                float v01 = fmaxf(acc[mi][ni][1] + bv1, 0.f) * pA;
                float v10 = fmaxf(acc[mi][ni][2] + bv0, 0.f) * pB;
                float v11 = fmaxf(acc[mi][ni][3] + bv1, 0.f) * pB;
                *(__half2*)&g_hs[(size_t)mA * HC + n] =
                    __half2(__float2half_rn(v00), __float2half_rn(v01));
                *(__half2*)&g_hs[(size_t)mB * HC + n] =
                    __half2(__float2half_rn(v10), __float2half_rn(v11));
            }
        }
    } else {
        float* part = g_part[blockIdx.x];
        #pragma unroll
        for (int mi = 0; mi < 4; mi++) {
            int mA = m0 + m_w + mi * 16 + trow;
            int mB = mA + 8;
            #pragma unroll
            for (int ni = 0; ni < 4; ni++) {
                int n = n_w + ni * 8 + tcol;
                *(float2*)&part[(size_t)mA * 128 + n] = make_float2(acc[mi][ni][0], acc[mi][ni][1]);
                *(float2*)&part[(size_t)mB * 128 + n] = make_float2(acc[mi][ni][2], acc[mi][ni][3]);
            }
        }
    }
}

// ============================================================
// Kernel 6: reduce split-K + leaf-weighted b2
// ============================================================
__global__ void k_reduce(const float* __restrict__ b2, float* __restrict__ out) {
    int idx = blockIdx.x * blockDim.x + threadIdx.x;
    if (idx >= B_ * NC) return;
    int b = idx / NC;
    int c = idx - b * NC;
    float v = 0.f;
    #pragma unroll
    for (int s = 0; s < KSPLIT2; s++) v += g_part[s][(size_t)b * 128 + c];
    float bias = 0.f;
    #pragma unroll
    for (int l = 0; l < NL; l++) bias += g_p[l * B_ + b] * b2[l * NC + c];
    out[idx] = v + bias;
}

extern "C" void kernel_launch(void* const* d_in, const int* in_sizes, int n_in,
                              void* d_out, int out_size) {
    const float* x   = (const float*)d_in[0];
    const float* u   = (const float*)d_in[1];
    const float* fl  = (const float*)d_in[2];
    const float* thr = (const float*)d_in[3];
    const float* fw  = (const float*)d_in[4];
    const float* W1  = (const float*)d_in[5];
    const float* b1  = (const float*)d_in[6];
    const float* W2  = (const float*)d_in[7];
    const float* b2  = (const float*)d_in[8];
    float* out = (float*)d_out;

    cudaFuncSetAttribute(k_gemm_tc<false>, cudaFuncAttributeMaxDynamicSharedMemorySize, SMEM_TOTAL);
    cudaFuncSetAttribute(k_gemm_tc<true>,  cudaFuncAttributeMaxDynamicSharedMemorySize, SMEM_TOTAL);

    // launch order: k_gemm_tc<false> stays launch #3 (profiled slot)
    k_prep<<<(N4X + N4W + N4P + N4F + 255) / 256, 256>>>(x, W1, W2, fl, fw);
    k_gumbel_split<<<NI * B_ / 8, 256>>>(x, u, thr);
    k_leaf_probs<<<B_ / 256, 256>>>();
    k_gemm_tc<false><<<dim3(HC / TILE_N, B_ / TILE_M), 256, SMEM_TOTAL>>>(b1);
    k_gemm_tc<true><<<dim3(KSPLIT2, B_ / TILE_M), 256, SMEM_TOTAL>>>(nullptr);
    k_reduce<<<(B_ * NC + 255) / 256, 256>>>(b2, out);
}